// round 9
// baseline (speedup 1.0000x reference)
#include <cuda_runtime.h>
#include <cuda_fp16.h>
#include <cstdint>

#define T_SEQ 512
#define B_SZ  128
#define HID   128
#define DEMB  300
#define KPAD  304     // padded to multiple of 16
#define MTOT  65536   // B*T

// single dynamic-smem symbol shared by all dynamic-smem kernels
extern __shared__ char k_smem[];

// ---------------- scratch (device globals; zero-init BSS) ----------------
__device__ float g_X0[MTOT * KPAD];        // padded embedded input, tf32-rounded
__device__ float g_Wpad[1024 * KPAD];      // concat(w_ih_l0f, w_ih_l0r), padded, tf32-rounded
__device__ float g_W1[512 * 256];          // w_ih_l1f, tf32-rounded
__device__ float g_bias0[1024];
__device__ float g_bias1f[512];
__device__ float g_bias1r[512];
__device__ float g_xg0[MTOT * 1024];       // layer0 input gates, both dirs
__device__ float g_hs0[MTOT * 256];        // layer0 output [b][t][fwd128|rev128] (tf32-rounded)
__device__ float g_xg1f[MTOT * 512];
__device__ float g_xg1r[128 * 512];
__device__ float g_h1last[128 * 256];      // [fwd h_T-1 | rev h_at_T-1]

// ---------------- helpers ----------------
__device__ __forceinline__ float sigf(float x) {
    return __fdividef(1.f, 1.f + __expf(-x));
}
__device__ __forceinline__ float tanh_fast(float x) {
    return 1.f - __fdividef(2.f, __expf(2.f * x) + 1.f);
}
__device__ __forceinline__ float rtf32(float x) {
    uint32_t u;
    asm("cvt.rna.tf32.f32 %0, %1;" : "=r"(u) : "f"(x));
    return __uint_as_float(u);
}
__device__ __forceinline__ float rcpf(float x) {
    float r; asm("rcp.approx.ftz.f32 %0, %1;" : "=f"(r) : "f"(x)); return r;
}
__device__ __forceinline__ uint32_t smem_u32(const void* p) {
    uint32_t a;
    asm("{ .reg .u64 t; cvta.to.shared.u64 t, %1; cvt.u32.u64 %0, t; }" : "=r"(a) : "l"(p));
    return a;
}
__device__ __forceinline__ uint32_t f2h2(float x, float y) {
    __half2 h = __floats2half2_rn(x, y);
    return *reinterpret_cast<uint32_t*>(&h);
}

__device__ __forceinline__ void cp16(void* s, const void* g) {
    uint32_t sa = smem_u32(s);
    asm volatile("cp.async.cg.shared.global [%0], [%1], 16;" :: "r"(sa), "l"(g));
}
#define CP_COMMIT() asm volatile("cp.async.commit_group;" ::: "memory")
#define CP_WAIT0()  asm volatile("cp.async.wait_group 0;" ::: "memory")

__device__ __forceinline__ void mma_tf32(float* c, const uint32_t* a,
                                         uint32_t b0, uint32_t b1) {
    asm volatile(
        "mma.sync.aligned.m16n8k8.row.col.f32.tf32.tf32.f32 "
        "{%0,%1,%2,%3}, {%4,%5,%6,%7}, {%8,%9}, {%0,%1,%2,%3};"
        : "+f"(c[0]), "+f"(c[1]), "+f"(c[2]), "+f"(c[3])
        : "r"(a[0]), "r"(a[1]), "r"(a[2]), "r"(a[3]), "r"(b0), "r"(b1));
}

__device__ __forceinline__ void mma_f16(float& c0, float& c1, float& c2, float& c3,
                                        uint32_t a0, uint32_t a1, uint32_t a2, uint32_t a3,
                                        uint32_t b0, uint32_t b1) {
    asm volatile(
        "mma.sync.aligned.m16n8k16.row.col.f32.f16.f16.f32 "
        "{%0,%1,%2,%3}, {%4,%5,%6,%7}, {%8,%9}, {%0,%1,%2,%3};"
        : "+f"(c0), "+f"(c1), "+f"(c2), "+f"(c3)
        : "r"(a0), "r"(a1), "r"(a2), "r"(a3), "r"(b0), "r"(b1));
}

// LSTM cell: c' = sig(f)c + sig(i)tanh(g); h = sig(o)tanh(c').
// Common-denominator form: 7 MUFU. Gates clamped to +-15.
__device__ __forceinline__ void lstm_cell(float gi, float gf, float gg, float go,
                                          float& c, float& h) {
    gi = fminf(fmaxf(gi, -15.f), 15.f);
    gf = fminf(fmaxf(gf, -15.f), 15.f);
    gg = fminf(fmaxf(gg, -15.f), 15.f);
    go = fminf(fmaxf(go, -15.f), 15.f);
    float ei = __expf(-gi), ef = __expf(-gf), eg = __expf(-2.f * gg);
    float pi = 1.f + ei, pf = 1.f + ef, pg = 1.f + eg;
    float num = c * (pi * pg) + pf * (1.f - eg);
    float cN = num * rcpf(pf * pi * pg);
    c = cN;
    float ch = fminf(fmaxf(cN, -15.f), 15.f);
    float eo = __expf(-go), ec = __expf(-2.f * ch);
    h = (1.f - ec) * rcpf((1.f + eo) * (1.f + ec));
}

// ---------------- prep: pad + tf32-round weights, combine biases ----------------
__global__ void prep_kernel(const float* __restrict__ wf, const float* __restrict__ wr,
                            const float* __restrict__ w1f,
                            const float* __restrict__ bif, const float* __restrict__ bhf,
                            const float* __restrict__ bir, const float* __restrict__ bhr,
                            const float* __restrict__ b1if, const float* __restrict__ b1hf,
                            const float* __restrict__ b1ir, const float* __restrict__ b1hr) {
    int idx = blockIdx.x * blockDim.x + threadIdx.x;
    int stride = gridDim.x * blockDim.x;
    for (int i = idx; i < 1024 * KPAD; i += stride) {
        int n = i / KPAD, k = i - n * KPAD;
        float v = 0.f;
        if (k < DEMB) v = (n < 512) ? wf[n * DEMB + k] : wr[(n - 512) * DEMB + k];
        g_Wpad[i] = rtf32(v);
    }
    for (int i = idx; i < 512 * 256; i += stride) g_W1[i] = rtf32(w1f[i]);
    if (idx < 1024)
        g_bias0[idx] = (idx < 512) ? (bif[idx] + bhf[idx]) : (bir[idx - 512] + bhr[idx - 512]);
    if (idx < 512) {
        g_bias1f[idx] = b1if[idx] + b1hf[idx];
        g_bias1r[idx] = b1ir[idx] + b1hr[idx];
    }
}

// ---------------- embedding gather (tf32-rounded store) ----------------
__global__ void embed_kernel(const int* __restrict__ x, const float* __restrict__ emb) {
    int idx = blockIdx.x * blockDim.x + threadIdx.x;
    int stride = gridDim.x * blockDim.x;
    const int total = MTOT * 75;  // 75 float4 per row (300 floats); cols 300..303 stay 0
    for (int i = idx; i < total; i += stride) {
        int m = i / 75, q = i - m * 75;
        int v = x[m];
        float4 val = *(const float4*)(emb + (long)v * DEMB + q * 4);
        float4 w = make_float4(rtf32(val.x), rtf32(val.y), rtf32(val.z), rtf32(val.w));
        *(float4*)(g_X0 + (long)m * KPAD + q * 4) = w;
    }
}

// ---------------- tensor-core tf32 GEMM (base-ISA mma.sync) ----------------
#define PAD_K 20
__global__ __launch_bounds__(256) void gemm_mma_kernel(
    const float* __restrict__ A, int lda,
    const float* __restrict__ B, int ldb,
    float* __restrict__ C, int ldc,
    int K, const float* __restrict__ bias) {
    __shared__ float As[2][128 * PAD_K];
    __shared__ float Bs[2][128 * PAD_K];

    const int tid = threadIdx.x;
    const int lane = tid & 31, wid = tid >> 5;
    const int wm = wid >> 1, wn = wid & 1;        // 4 x 2 warp grid
    const int g = lane >> 2, t = lane & 3;
    const int bm = blockIdx.y * 128, bn = blockIdx.x * 128;

    float c[2][8][4];
#pragma unroll
    for (int mt = 0; mt < 2; mt++)
#pragma unroll
        for (int nt = 0; nt < 8; nt++)
#pragma unroll
            for (int j = 0; j < 4; j++) c[mt][nt][j] = 0.f;

    const int nit = K / 16;
    auto load_stage = [&](int it, int p) {
#pragma unroll
        for (int i = tid; i < 512; i += 256) {
            int r = i >> 2, q = i & 3;
            cp16(&As[p][r * PAD_K + q * 4], A + (long)(bm + r) * lda + it * 16 + q * 4);
        }
#pragma unroll
        for (int i = tid; i < 512; i += 256) {
            int r = i >> 2, q = i & 3;
            cp16(&Bs[p][r * PAD_K + q * 4], B + (long)(bn + r) * ldb + it * 16 + q * 4);
        }
        CP_COMMIT();
    };

    load_stage(0, 0);
    for (int it = 0; it < nit; it++) {
        CP_WAIT0();
        __syncthreads();
        if (it + 1 < nit) load_stage(it + 1, (it + 1) & 1);
        const int p = it & 1;
        const float* Ab = As[p] + (wm * 32) * PAD_K;
        const float* Bb = Bs[p] + (wn * 64) * PAD_K;
#pragma unroll
        for (int ks = 0; ks < 2; ks++) {
            const int k0 = ks * 8;
            uint32_t afr[2][4];
#pragma unroll
            for (int mt = 0; mt < 2; mt++) {
                const float* r0 = Ab + (mt * 16 + g) * PAD_K + k0 + t;
                const float* r1 = r0 + 8 * PAD_K;
                afr[mt][0] = __float_as_uint(r0[0]);
                afr[mt][1] = __float_as_uint(r1[0]);
                afr[mt][2] = __float_as_uint(r0[4]);
                afr[mt][3] = __float_as_uint(r1[4]);
            }
#pragma unroll
            for (int nt = 0; nt < 8; nt++) {
                const float* br = Bb + (nt * 8 + g) * PAD_K + k0 + t;
                uint32_t b0 = __float_as_uint(br[0]);
                uint32_t b1 = __float_as_uint(br[4]);
                mma_tf32(c[0][nt], afr[0], b0, b1);
                mma_tf32(c[1][nt], afr[1], b0, b1);
            }
        }
        __syncthreads();
    }

#pragma unroll
    for (int mt = 0; mt < 2; mt++) {
        const int row = bm + wm * 32 + mt * 16 + g;
#pragma unroll
        for (int nt = 0; nt < 8; nt++) {
            const int col = bn + wn * 64 + nt * 8 + 2 * t;
            float2 bb = *(const float2*)(bias + col);
            float2 o0 = make_float2(c[mt][nt][0] + bb.x, c[mt][nt][1] + bb.y);
            float2 o1 = make_float2(c[mt][nt][2] + bb.x, c[mt][nt][3] + bb.y);
            *(float2*)(C + (long)row * ldc + col) = o0;
            *(float2*)(C + (long)(row + 8) * ldc + col) = o1;
        }
    }
}

// ---------------- fp32 tiled GEMM (tiny layer-1 reverse GEMM only) ----------------
__global__ __launch_bounds__(256) void gemm_bias_kernel(
    const float* __restrict__ A, int lda,
    const float* __restrict__ B, int ldb,
    float* __restrict__ C, int ldc,
    int K, const float* __restrict__ bias) {
    __shared__ float As[16][132];
    __shared__ float Bs[16][68];

    const int tid = threadIdx.x;
    const int bm = blockIdx.y * 128, bn = blockIdx.x * 64;
    const int tx = tid & 15, ty = tid >> 4;
    const int arow = tid >> 2, acol = tid & 3;

    float acc[8][4];
#pragma unroll
    for (int i = 0; i < 8; i++)
#pragma unroll
        for (int j = 0; j < 4; j++) acc[i][j] = 0.f;

    const float* Aptr = A + (long)(bm + arow) * lda + acol * 4;
    const float* Bptr = B + (long)(bn + arow) * ldb + acol * 4;

    for (int k0 = 0; k0 < K; k0 += 16) {
        float4 a0 = *(const float4*)(Aptr + k0);
        float4 a1 = *(const float4*)(Aptr + (long)64 * lda + k0);
        float4 b0 = *(const float4*)(Bptr + k0);
        __syncthreads();
        As[acol * 4 + 0][arow] = a0.x; As[acol * 4 + 1][arow] = a0.y;
        As[acol * 4 + 2][arow] = a0.z; As[acol * 4 + 3][arow] = a0.w;
        As[acol * 4 + 0][arow + 64] = a1.x; As[acol * 4 + 1][arow + 64] = a1.y;
        As[acol * 4 + 2][arow + 64] = a1.z; As[acol * 4 + 3][arow + 64] = a1.w;
        Bs[acol * 4 + 0][arow] = b0.x; Bs[acol * 4 + 1][arow] = b0.y;
        Bs[acol * 4 + 2][arow] = b0.z; Bs[acol * 4 + 3][arow] = b0.w;
        __syncthreads();
#pragma unroll
        for (int k = 0; k < 16; k++) {
            float4 av0 = *(float4*)&As[k][ty * 8];
            float4 av1 = *(float4*)&As[k][ty * 8 + 4];
            float4 bv  = *(float4*)&Bs[k][tx * 4];
            float a[8] = {av0.x, av0.y, av0.z, av0.w, av1.x, av1.y, av1.z, av1.w};
            float b[4] = {bv.x, bv.y, bv.z, bv.w};
#pragma unroll
            for (int i = 0; i < 8; i++)
#pragma unroll
                for (int j = 0; j < 4; j++) acc[i][j] = fmaf(a[i], b[j], acc[i][j]);
        }
    }
    float4 bb = *(const float4*)(bias + bn + tx * 4);
#pragma unroll
    for (int i = 0; i < 8; i++) {
        float4 o;
        o.x = acc[i][0] + bb.x; o.y = acc[i][1] + bb.y;
        o.z = acc[i][2] + bb.z; o.w = acc[i][3] + bb.w;
        *(float4*)(C + (long)(bm + ty * 8 + i) * ldc + bn + tx * 4) = o;
    }
}

// ---------------- LSTM recurrence: fused MMA + in-register cell update ----------------
// 512 threads = 16 warps, 8 batch rows per CTA. Warp w owns columns w*8..w*8+7 of
// EACH gate block (i/f/g/o at nt*128 + w*8): after the MMA, thread (gq,c4) holds all
// 4 gates for cells (row gq, j=w*8+2c4, +1) in registers -> elementwise is in-register,
// no gate smem roundtrip, ONE __syncthreads per step. H double-buffered fp16x2 in smem.
#define MR 8
#define HP 68    // Hsh2 row stride (fp16x2 words)
template <int NDIR, bool WRITE_ALL>
__global__ __launch_bounds__(512, 1)
void lstm_mma_kernel(const float* __restrict__ xg, int gst,
                     const float* __restrict__ whh_f, const float* __restrict__ whh_r,
                     float* __restrict__ out) {
    uint32_t* Hsh2 = (uint32_t*)k_smem;       // [2][8][HP] fp16x2 pairs of h

    const int tid = threadIdx.x;
    const int lane = tid & 31, w = tid >> 5;
    const int gq = lane >> 2, c4 = lane & 3;
    int dir, chunk;
    if (NDIR == 2) { dir = blockIdx.x & 1; chunk = blockIdx.x >> 1; }
    else           { dir = 0;              chunk = blockIdx.x; }
    const int row0 = chunk * MR;
    const float* whh = (dir == 0) ? whh_f : whh_r;
    const int goff = (NDIR == 2) ? dir * 512 : 0;

    // ---- pack w_hh B-fragments (fp16), once; nt indexes the GATE block ----
    uint32_t bfrag[4][8][2];
#pragma unroll
    for (int nt = 0; nt < 4; nt++) {
        const int n = nt * 128 + w * 8 + gq;
        const float* wp = whh + n * 128;
#pragma unroll
        for (int kt = 0; kt < 8; kt++) {
            float2 v0 = *(const float2*)(wp + kt * 16 + 2 * c4);
            float2 v1 = *(const float2*)(wp + kt * 16 + 2 * c4 + 8);
            bfrag[nt][kt][0] = f2h2(v0.x, v0.y);
            bfrag[nt][kt][1] = f2h2(v1.x, v1.y);
        }
    }
    for (int i = tid; i < MR * HP; i += 512) Hsh2[i] = 0;  // zero buffer 0
    __syncthreads();

    // this thread's cells: row gq, columns j0, j0+1
    const int j0 = w * 8 + 2 * c4;
    float cr0 = 0.f, cr1 = 0.f;
    const float* xrow = xg + (long)(row0 + gq) * T_SEQ * gst + goff + j0;

    float2 xi, xf, xgv, xo;
    {
        const int t0 = (dir == 0) ? 0 : (T_SEQ - 1);
        const float* b = xrow + (long)t0 * gst;
        xi = *(const float2*)(b);        xf = *(const float2*)(b + 128);
        xgv = *(const float2*)(b + 256); xo = *(const float2*)(b + 384);
    }

    for (int s = 0; s < T_SEQ; s++) {
        const int t = (dir == 0) ? s : (T_SEQ - 1 - s);
        const uint32_t* Hrd = Hsh2 + (s & 1) * (MR * HP);
        uint32_t* Hwr = Hsh2 + ((s + 1) & 1) * (MR * HP);

        // ---- A-fragments of H (fp16x2) ----
        uint32_t a0[8], a2[8];
#pragma unroll
        for (int kt = 0; kt < 8; kt++) {
            a0[kt] = Hrd[gq * HP + kt * 8 + c4];
            a2[kt] = Hrd[gq * HP + kt * 8 + c4 + 4];
        }

        // prefetch next-step xg (covered by MMA + elementwise)
        float2 ni, nf, ng, no;
        if (s + 1 < T_SEQ) {
            const int tn = (dir == 0) ? (s + 1) : (T_SEQ - 2 - s);
            const float* b = xrow + (long)tn * gst;
            ni = *(const float2*)(b);       nf = *(const float2*)(b + 128);
            ng = *(const float2*)(b + 256); no = *(const float2*)(b + 384);
        }

        // ---- gate MMA: 4 gate blocks x 8 k-tiles ----
        float cf[4][2];
#pragma unroll
        for (int nt = 0; nt < 4; nt++) { cf[nt][0] = 0.f; cf[nt][1] = 0.f; }
        float dz0 = 0.f, dz1 = 0.f;  // zero-row sinks
#pragma unroll
        for (int kt = 0; kt < 8; kt++)
#pragma unroll
            for (int nt = 0; nt < 4; nt++)
                mma_f16(cf[nt][0], cf[nt][1], dz0, dz1,
                        a0[kt], 0u, a2[kt], 0u, bfrag[nt][kt][0], bfrag[nt][kt][1]);

        // ---- in-register cell update (2 cells) ----
        float h0, h1;
        lstm_cell(cf[0][0] + xi.x, cf[1][0] + xf.x, cf[2][0] + xgv.x, cf[3][0] + xo.x, cr0, h0);
        lstm_cell(cf[0][1] + xi.y, cf[1][1] + xf.y, cf[2][1] + xgv.y, cf[3][1] + xo.y, cr1, h1);
        Hwr[gq * HP + w * 4 + c4] = f2h2(h0, h1);
        if (WRITE_ALL) {
            *(float2*)&out[((long)(row0 + gq) * T_SEQ + t) * 256 + dir * 128 + j0] =
                make_float2(rtf32(h0), rtf32(h1));
        } else if (s == T_SEQ - 1) {
            *(float2*)&out[(row0 + gq) * 256 + j0] = make_float2(h0, h1);
        }
        __syncthreads();
        xi = ni; xf = nf; xgv = ng; xo = no;
    }
}

// ---------------- layer1 reverse: single step with h0=0 -> pure elementwise ----------------
__global__ void l1rev_kernel() {
    int idx = blockIdx.x * blockDim.x + threadIdx.x;
    if (idx >= 128 * 128) return;
    int b = idx >> 7, j = idx & 127;
    const float* xg = g_xg1r + b * 512;
    float iv = xg[j], gv = xg[256 + j], ov = xg[384 + j];
    float c = sigf(iv) * tanh_fast(gv);
    g_h1last[b * 256 + 128 + j] = sigf(ov) * tanh_fast(c);
}

// ---------------- final FC ----------------
__global__ void fc_kernel(const float* __restrict__ fcw, const float* __restrict__ fcb,
                          float* __restrict__ out) {
    int b = blockIdx.x;
    int lane = threadIdx.x;
    float v[8];
#pragma unroll
    for (int u = 0; u < 8; u++) v[u] = g_h1last[b * 256 + lane + u * 32];
    for (int c = 0; c < 10; c++) {
        float s = 0.f;
#pragma unroll
        for (int u = 0; u < 8; u++) s = fmaf(v[u], fcw[c * 256 + lane + u * 32], s);
#pragma unroll
        for (int o = 16; o; o >>= 1) s += __shfl_xor_sync(0xffffffffu, s, o);
        if (lane == 0) out[b * 10 + c] = s + fcb[c];
    }
}

// ---------------- launch ----------------
extern "C" void kernel_launch(void* const* d_in, const int* in_sizes, int n_in,
                              void* d_out, int out_size) {
    const int*   x        = (const int*)d_in[0];
    const float* emb      = (const float*)d_in[1];
    const float* wih_l0f  = (const float*)d_in[2];
    const float* whh_l0f  = (const float*)d_in[3];
    const float* bih_l0f  = (const float*)d_in[4];
    const float* bhh_l0f  = (const float*)d_in[5];
    const float* wih_l0r  = (const float*)d_in[6];
    const float* whh_l0r  = (const float*)d_in[7];
    const float* bih_l0r  = (const float*)d_in[8];
    const float* bhh_l0r  = (const float*)d_in[9];
    const float* wih_l1f  = (const float*)d_in[10];
    const float* whh_l1f  = (const float*)d_in[11];
    const float* bih_l1f  = (const float*)d_in[12];
    const float* bhh_l1f  = (const float*)d_in[13];
    const float* wih_l1r  = (const float*)d_in[14];
    const float* bih_l1r  = (const float*)d_in[16];
    const float* bhh_l1r  = (const float*)d_in[17];
    const float* fc_w     = (const float*)d_in[18];
    const float* fc_b     = (const float*)d_in[19];
    float* out = (float*)d_out;

    float *pX0, *pWpad, *pW1, *pB0, *pB1f, *pB1r, *pXg0, *pHs0, *pXg1f, *pXg1r, *pH1;
    cudaGetSymbolAddress((void**)&pX0,   g_X0);
    cudaGetSymbolAddress((void**)&pWpad, g_Wpad);
    cudaGetSymbolAddress((void**)&pW1,   g_W1);
    cudaGetSymbolAddress((void**)&pB0,   g_bias0);
    cudaGetSymbolAddress((void**)&pB1f,  g_bias1f);
    cudaGetSymbolAddress((void**)&pB1r,  g_bias1r);
    cudaGetSymbolAddress((void**)&pXg0,  g_xg0);
    cudaGetSymbolAddress((void**)&pHs0,  g_hs0);
    cudaGetSymbolAddress((void**)&pXg1f, g_xg1f);
    cudaGetSymbolAddress((void**)&pXg1r, g_xg1r);
    cudaGetSymbolAddress((void**)&pH1,   g_h1last);

    const int SMEM_SCAN = 2 * MR * HP * 4;   // 4352 B

    prep_kernel<<<128, 256>>>(wih_l0f, wih_l0r, wih_l1f,
                              bih_l0f, bhh_l0f, bih_l0r, bhh_l0r,
                              bih_l1f, bhh_l1f, bih_l1r, bhh_l1r);
    embed_kernel<<<2048, 256>>>(x, emb);

    // layer 0 input gates (tensor cores via mma.sync tf32): [65536,304] x [1024,304]^T
    {
        dim3 grid(1024 / 128, MTOT / 128);
        gemm_mma_kernel<<<grid, 256>>>(pX0, KPAD, pWpad, KPAD, pXg0, 1024, KPAD, pB0);
    }
    // layer 0 scan (both dirs): 32 CTAs, fused MMA recurrence
    lstm_mma_kernel<2, true><<<32, 512, SMEM_SCAN>>>(pXg0, 1024, whh_l0f, whh_l0r, pHs0);

    // layer 1 forward input gates (tensor cores): [65536,256] x [512,256]^T
    {
        dim3 grid(512 / 128, MTOT / 128);
        gemm_mma_kernel<<<grid, 256>>>(pHs0, 256, pW1, 256, pXg1f, 512, 256, pB1f);
    }
    // layer 1 reverse: only t=T-1 row needed -> tiny GEMM (M=128), fp32 SIMT
    {
        dim3 grid(512 / 64, 1);
        gemm_bias_kernel<<<grid, 256>>>(pHs0 + 511 * 256, T_SEQ * 256, wih_l1r, 256,
                                        pXg1r, 512, 256, pB1r);
    }
    // layer 1 forward scan (only final h needed): 16 CTAs, fused MMA recurrence
    lstm_mma_kernel<1, false><<<16, 512, SMEM_SCAN>>>(pXg1f, 512, whh_l1f, whh_l1f, pH1);
    // layer 1 reverse: single step, elementwise
    l1rev_kernel<<<64, 256>>>();

    fc_kernel<<<128, 32>>>(fc_w, fc_b, out);
    (void)in_sizes; (void)n_in; (void)out_size;
}

// round 10
// speedup vs baseline: 1.1668x; 1.1668x over previous
#include <cuda_runtime.h>
#include <cuda_fp16.h>
#include <cstdint>

#define T_SEQ 512
#define B_SZ  128
#define HID   128
#define DEMB  300
#define KPAD  304     // padded to multiple of 16
#define MTOT  65536   // B*T

// single dynamic-smem symbol shared by all dynamic-smem kernels
extern __shared__ char k_smem[];

// ---------------- scratch (device globals; zero-init BSS) ----------------
__device__ float g_X0[MTOT * KPAD];        // padded embedded input, tf32-rounded
__device__ float g_Wpad[1024 * KPAD];      // concat(w_ih_l0f, w_ih_l0r), padded, tf32-rounded
__device__ float g_W1[512 * 256];          // w_ih_l1f, tf32-rounded
__device__ float g_bias0[1024];
__device__ float g_bias1f[512];
__device__ float g_bias1r[512];
__device__ float g_xg0[MTOT * 1024];       // layer0 input gates, both dirs
__device__ float g_hs0[MTOT * 256];        // layer0 output [b][t][fwd128|rev128] (tf32-rounded)
__device__ float g_xg1f[MTOT * 512];
__device__ float g_xg1r[128 * 512];
__device__ float g_h1last[128 * 256];      // [fwd h_T-1 | rev h_at_T-1]

// ---------------- helpers ----------------
__device__ __forceinline__ float sigf(float x) {
    return __fdividef(1.f, 1.f + __expf(-x));
}
__device__ __forceinline__ float tanh_fast(float x) {
    return 1.f - __fdividef(2.f, __expf(2.f * x) + 1.f);
}
__device__ __forceinline__ float rtf32(float x) {
    uint32_t u;
    asm("cvt.rna.tf32.f32 %0, %1;" : "=r"(u) : "f"(x));
    return __uint_as_float(u);
}
__device__ __forceinline__ float rcpf(float x) {
    float r; asm("rcp.approx.ftz.f32 %0, %1;" : "=f"(r) : "f"(x)); return r;
}
__device__ __forceinline__ uint32_t smem_u32(const void* p) {
    uint32_t a;
    asm("{ .reg .u64 t; cvta.to.shared.u64 t, %1; cvt.u32.u64 %0, t; }" : "=r"(a) : "l"(p));
    return a;
}
__device__ __forceinline__ uint32_t f2h2(float x, float y) {
    __half2 h = __floats2half2_rn(x, y);
    return *reinterpret_cast<uint32_t*>(&h);
}

__device__ __forceinline__ void cp16(void* s, const void* g) {
    uint32_t sa = smem_u32(s);
    asm volatile("cp.async.cg.shared.global [%0], [%1], 16;" :: "r"(sa), "l"(g));
}
#define CP_COMMIT() asm volatile("cp.async.commit_group;" ::: "memory")
#define CP_WAIT0()  asm volatile("cp.async.wait_group 0;" ::: "memory")

__device__ __forceinline__ void mma_tf32(float* c, const uint32_t* a,
                                         uint32_t b0, uint32_t b1) {
    asm volatile(
        "mma.sync.aligned.m16n8k8.row.col.f32.tf32.tf32.f32 "
        "{%0,%1,%2,%3}, {%4,%5,%6,%7}, {%8,%9}, {%0,%1,%2,%3};"
        : "+f"(c[0]), "+f"(c[1]), "+f"(c[2]), "+f"(c[3])
        : "r"(a[0]), "r"(a[1]), "r"(a[2]), "r"(a[3]), "r"(b0), "r"(b1));
}

__device__ __forceinline__ void mma_f16(float& c0, float& c1, float& c2, float& c3,
                                        uint32_t a0, uint32_t a1, uint32_t a2, uint32_t a3,
                                        uint32_t b0, uint32_t b1) {
    asm volatile(
        "mma.sync.aligned.m16n8k16.row.col.f32.f16.f16.f32 "
        "{%0,%1,%2,%3}, {%4,%5,%6,%7}, {%8,%9}, {%0,%1,%2,%3};"
        : "+f"(c0), "+f"(c1), "+f"(c2), "+f"(c3)
        : "r"(a0), "r"(a1), "r"(a2), "r"(a3), "r"(b0), "r"(b1));
}

// LSTM cell: c' = sig(f)c + sig(i)tanh(g); h = sig(o)tanh(c').
// Common-denominator form: 7 MUFU. Gates clamped to +-15.
__device__ __forceinline__ void lstm_cell(float gi, float gf, float gg, float go,
                                          float& c, float& h) {
    gi = fminf(fmaxf(gi, -15.f), 15.f);
    gf = fminf(fmaxf(gf, -15.f), 15.f);
    gg = fminf(fmaxf(gg, -15.f), 15.f);
    go = fminf(fmaxf(go, -15.f), 15.f);
    float ei = __expf(-gi), ef = __expf(-gf), eg = __expf(-2.f * gg);
    float pi = 1.f + ei, pf = 1.f + ef, pg = 1.f + eg;
    float num = c * (pi * pg) + pf * (1.f - eg);
    float cN = num * rcpf(pf * pi * pg);
    c = cN;
    float ch = fminf(fmaxf(cN, -15.f), 15.f);
    float eo = __expf(-go), ec = __expf(-2.f * ch);
    h = (1.f - ec) * rcpf((1.f + eo) * (1.f + ec));
}

// ---------------- prep: pad + tf32-round weights, combine biases ----------------
__global__ void prep_kernel(const float* __restrict__ wf, const float* __restrict__ wr,
                            const float* __restrict__ w1f,
                            const float* __restrict__ bif, const float* __restrict__ bhf,
                            const float* __restrict__ bir, const float* __restrict__ bhr,
                            const float* __restrict__ b1if, const float* __restrict__ b1hf,
                            const float* __restrict__ b1ir, const float* __restrict__ b1hr) {
    int idx = blockIdx.x * blockDim.x + threadIdx.x;
    int stride = gridDim.x * blockDim.x;
    for (int i = idx; i < 1024 * KPAD; i += stride) {
        int n = i / KPAD, k = i - n * KPAD;
        float v = 0.f;
        if (k < DEMB) v = (n < 512) ? wf[n * DEMB + k] : wr[(n - 512) * DEMB + k];
        g_Wpad[i] = rtf32(v);
    }
    for (int i = idx; i < 512 * 256; i += stride) g_W1[i] = rtf32(w1f[i]);
    if (idx < 1024)
        g_bias0[idx] = (idx < 512) ? (bif[idx] + bhf[idx]) : (bir[idx - 512] + bhr[idx - 512]);
    if (idx < 512) {
        g_bias1f[idx] = b1if[idx] + b1hf[idx];
        g_bias1r[idx] = b1ir[idx] + b1hr[idx];
    }
}

// ---------------- embedding gather (tf32-rounded store) ----------------
__global__ void embed_kernel(const int* __restrict__ x, const float* __restrict__ emb) {
    int idx = blockIdx.x * blockDim.x + threadIdx.x;
    int stride = gridDim.x * blockDim.x;
    const int total = MTOT * 75;  // 75 float4 per row (300 floats); cols 300..303 stay 0
    for (int i = idx; i < total; i += stride) {
        int m = i / 75, q = i - m * 75;
        int v = x[m];
        float4 val = *(const float4*)(emb + (long)v * DEMB + q * 4);
        float4 w = make_float4(rtf32(val.x), rtf32(val.y), rtf32(val.z), rtf32(val.w));
        *(float4*)(g_X0 + (long)m * KPAD + q * 4) = w;
    }
}

// ---------------- tensor-core tf32 GEMM (base-ISA mma.sync) ----------------
#define PAD_K 20
__global__ __launch_bounds__(256) void gemm_mma_kernel(
    const float* __restrict__ A, int lda,
    const float* __restrict__ B, int ldb,
    float* __restrict__ C, int ldc,
    int K, const float* __restrict__ bias) {
    __shared__ float As[2][128 * PAD_K];
    __shared__ float Bs[2][128 * PAD_K];

    const int tid = threadIdx.x;
    const int lane = tid & 31, wid = tid >> 5;
    const int wm = wid >> 1, wn = wid & 1;        // 4 x 2 warp grid
    const int g = lane >> 2, t = lane & 3;
    const int bm = blockIdx.y * 128, bn = blockIdx.x * 128;

    float c[2][8][4];
#pragma unroll
    for (int mt = 0; mt < 2; mt++)
#pragma unroll
        for (int nt = 0; nt < 8; nt++)
#pragma unroll
            for (int j = 0; j < 4; j++) c[mt][nt][j] = 0.f;

    const int nit = K / 16;
    auto load_stage = [&](int it, int p) {
#pragma unroll
        for (int i = tid; i < 512; i += 256) {
            int r = i >> 2, q = i & 3;
            cp16(&As[p][r * PAD_K + q * 4], A + (long)(bm + r) * lda + it * 16 + q * 4);
        }
#pragma unroll
        for (int i = tid; i < 512; i += 256) {
            int r = i >> 2, q = i & 3;
            cp16(&Bs[p][r * PAD_K + q * 4], B + (long)(bn + r) * ldb + it * 16 + q * 4);
        }
        CP_COMMIT();
    };

    load_stage(0, 0);
    for (int it = 0; it < nit; it++) {
        CP_WAIT0();
        __syncthreads();
        if (it + 1 < nit) load_stage(it + 1, (it + 1) & 1);
        const int p = it & 1;
        const float* Ab = As[p] + (wm * 32) * PAD_K;
        const float* Bb = Bs[p] + (wn * 64) * PAD_K;
#pragma unroll
        for (int ks = 0; ks < 2; ks++) {
            const int k0 = ks * 8;
            uint32_t afr[2][4];
#pragma unroll
            for (int mt = 0; mt < 2; mt++) {
                const float* r0 = Ab + (mt * 16 + g) * PAD_K + k0 + t;
                const float* r1 = r0 + 8 * PAD_K;
                afr[mt][0] = __float_as_uint(r0[0]);
                afr[mt][1] = __float_as_uint(r1[0]);
                afr[mt][2] = __float_as_uint(r0[4]);
                afr[mt][3] = __float_as_uint(r1[4]);
            }
#pragma unroll
            for (int nt = 0; nt < 8; nt++) {
                const float* br = Bb + (nt * 8 + g) * PAD_K + k0 + t;
                uint32_t b0 = __float_as_uint(br[0]);
                uint32_t b1 = __float_as_uint(br[4]);
                mma_tf32(c[0][nt], afr[0], b0, b1);
                mma_tf32(c[1][nt], afr[1], b0, b1);
            }
        }
        __syncthreads();
    }

#pragma unroll
    for (int mt = 0; mt < 2; mt++) {
        const int row = bm + wm * 32 + mt * 16 + g;
#pragma unroll
        for (int nt = 0; nt < 8; nt++) {
            const int col = bn + wn * 64 + nt * 8 + 2 * t;
            float2 bb = *(const float2*)(bias + col);
            float2 o0 = make_float2(c[mt][nt][0] + bb.x, c[mt][nt][1] + bb.y);
            float2 o1 = make_float2(c[mt][nt][2] + bb.x, c[mt][nt][3] + bb.y);
            *(float2*)(C + (long)row * ldc + col) = o0;
            *(float2*)(C + (long)(row + 8) * ldc + col) = o1;
        }
    }
}

// ---------------- fp32 tiled GEMM (tiny layer-1 reverse GEMM only) ----------------
__global__ __launch_bounds__(256) void gemm_bias_kernel(
    const float* __restrict__ A, int lda,
    const float* __restrict__ B, int ldb,
    float* __restrict__ C, int ldc,
    int K, const float* __restrict__ bias) {
    __shared__ float As[16][132];
    __shared__ float Bs[16][68];

    const int tid = threadIdx.x;
    const int bm = blockIdx.y * 128, bn = blockIdx.x * 64;
    const int tx = tid & 15, ty = tid >> 4;
    const int arow = tid >> 2, acol = tid & 3;

    float acc[8][4];
#pragma unroll
    for (int i = 0; i < 8; i++)
#pragma unroll
        for (int j = 0; j < 4; j++) acc[i][j] = 0.f;

    const float* Aptr = A + (long)(bm + arow) * lda + acol * 4;
    const float* Bptr = B + (long)(bn + arow) * ldb + acol * 4;

    for (int k0 = 0; k0 < K; k0 += 16) {
        float4 a0 = *(const float4*)(Aptr + k0);
        float4 a1 = *(const float4*)(Aptr + (long)64 * lda + k0);
        float4 b0 = *(const float4*)(Bptr + k0);
        __syncthreads();
        As[acol * 4 + 0][arow] = a0.x; As[acol * 4 + 1][arow] = a0.y;
        As[acol * 4 + 2][arow] = a0.z; As[acol * 4 + 3][arow] = a0.w;
        As[acol * 4 + 0][arow + 64] = a1.x; As[acol * 4 + 1][arow + 64] = a1.y;
        As[acol * 4 + 2][arow + 64] = a1.z; As[acol * 4 + 3][arow + 64] = a1.w;
        Bs[acol * 4 + 0][arow] = b0.x; Bs[acol * 4 + 1][arow] = b0.y;
        Bs[acol * 4 + 2][arow] = b0.z; Bs[acol * 4 + 3][arow] = b0.w;
        __syncthreads();
#pragma unroll
        for (int k = 0; k < 16; k++) {
            float4 av0 = *(float4*)&As[k][ty * 8];
            float4 av1 = *(float4*)&As[k][ty * 8 + 4];
            float4 bv  = *(float4*)&Bs[k][tx * 4];
            float a[8] = {av0.x, av0.y, av0.z, av0.w, av1.x, av1.y, av1.z, av1.w};
            float b[4] = {bv.x, bv.y, bv.z, bv.w};
#pragma unroll
            for (int i = 0; i < 8; i++)
#pragma unroll
                for (int j = 0; j < 4; j++) acc[i][j] = fmaf(a[i], b[j], acc[i][j]);
        }
    }
    float4 bb = *(const float4*)(bias + bn + tx * 4);
#pragma unroll
    for (int i = 0; i < 8; i++) {
        float4 o;
        o.x = acc[i][0] + bb.x; o.y = acc[i][1] + bb.y;
        o.z = acc[i][2] + bb.z; o.w = acc[i][3] + bb.w;
        *(float4*)(C + (long)(bm + ty * 8 + i) * ldc + bn + tx * 4) = o;
    }
}

// ---------------- LSTM recurrence: fused MMA + in-register cells + smem-staged IO ----------------
// 512 threads = 16 warps, 8 batch rows per CTA. Warp w owns columns w*8..w*8+7 of each
// gate block -> gates live in MMA accumulators, elementwise fully in-register.
// xg staged via cp.async into Xs (coalesced GMEM), read via LDS; out staged via Os
// (fragment-order STS, coalesced STG next step). ONE __syncthreads per step.
#define MR  8
#define HP  68    // H fp16x2 row stride
#define XsP 516   // Xs fp32 row stride
#define OsP 132   // Os fp32 row stride
template <int NDIR, bool WRITE_ALL>
__global__ __launch_bounds__(512, 1)
void lstm_mma_kernel(const float* __restrict__ xg, int gst,
                     const float* __restrict__ whh_f, const float* __restrict__ whh_r,
                     float* __restrict__ out) {
    uint32_t* Hsh2 = (uint32_t*)k_smem;                  // [2][MR][HP] fp16x2
    float* Xs = (float*)k_smem + 2 * MR * HP;            // [2][MR][XsP]
    float* Os = Xs + 2 * MR * XsP;                       // [2][MR][OsP] (WRITE_ALL only)

    const int tid = threadIdx.x;
    const int lane = tid & 31, w = tid >> 5;
    const int gq = lane >> 2, c4 = lane & 3;
    int dir, chunk;
    if (NDIR == 2) { dir = blockIdx.x & 1; chunk = blockIdx.x >> 1; }
    else           { dir = 0;              chunk = blockIdx.x; }
    const int row0 = chunk * MR;
    const float* whh = (dir == 0) ? whh_f : whh_r;
    const int goff = (NDIR == 2) ? dir * 512 : 0;

    // ---- pack w_hh B-fragments (fp16), once; nt indexes the GATE block ----
    uint32_t bfrag[4][8][2];
#pragma unroll
    for (int nt = 0; nt < 4; nt++) {
        const int n = nt * 128 + w * 8 + gq;
        const float* wp = whh + n * 128;
#pragma unroll
        for (int kt = 0; kt < 8; kt++) {
            float2 v0 = *(const float2*)(wp + kt * 16 + 2 * c4);
            float2 v1 = *(const float2*)(wp + kt * 16 + 2 * c4 + 8);
            bfrag[nt][kt][0] = f2h2(v0.x, v0.y);
            bfrag[nt][kt][1] = f2h2(v1.x, v1.y);
        }
    }
    for (int i = tid; i < MR * HP; i += 512) Hsh2[i] = 0;  // zero buffer 0

    // helper-IO mapping: 1024 chunks of 16B (8 rows x 128 chunks); thread -> 2 chunks
    const int hr0 = (2 * tid) >> 7, hc0 = ((2 * tid) & 127) * 4;
    const int hr1 = (2 * tid + 1) >> 7, hc1 = ((2 * tid + 1) & 127) * 4;
    // out-writer mapping (coalesced)
    const int em = tid >> 6, eq = tid & 63;

    // prefetch xg for step 0 into Xs[0]
    {
        const int t0 = (dir == 0) ? 0 : (T_SEQ - 1);
        cp16(&Xs[hr0 * XsP + hc0],
             xg + ((long)(row0 + hr0) * T_SEQ + t0) * gst + goff + hc0);
        cp16(&Xs[hr1 * XsP + hc1],
             xg + ((long)(row0 + hr1) * T_SEQ + t0) * gst + goff + hc1);
        CP_COMMIT(); CP_WAIT0();
    }
    __syncthreads();

    const int j0 = w * 8 + 2 * c4;   // this thread's cell columns (row gq)
    float cr0 = 0.f, cr1 = 0.f;

    for (int s = 0; s < T_SEQ; s++) {
        const int t = (dir == 0) ? s : (T_SEQ - 1 - s);
        const uint32_t* Hrd = Hsh2 + (s & 1) * (MR * HP);
        uint32_t* Hwr = Hsh2 + ((s + 1) & 1) * (MR * HP);
        const float* Xrd = Xs + (s & 1) * (MR * XsP);
        float* Xwr = Xs + ((s + 1) & 1) * (MR * XsP);

        // issue next-step xg prefetch (cp.async; lands before end-of-step wait)
        if (s + 1 < T_SEQ) {
            const int tn = (dir == 0) ? (s + 1) : (T_SEQ - 2 - s);
            cp16(&Xwr[hr0 * XsP + hc0],
                 xg + ((long)(row0 + hr0) * T_SEQ + tn) * gst + goff + hc0);
            cp16(&Xwr[hr1 * XsP + hc1],
                 xg + ((long)(row0 + hr1) * T_SEQ + tn) * gst + goff + hc1);
        }
        CP_COMMIT();

        // coalesced out-write of PREVIOUS step's h (from Os)
        if (WRITE_ALL && s > 0) {
            const int tp = (dir == 0) ? (s - 1) : (T_SEQ - s);
            float2 hv = *(const float2*)&Os[((s - 1) & 1) * (MR * OsP) + em * OsP + 2 * eq];
            *(float2*)&out[((long)(row0 + em) * T_SEQ + tp) * 256 + dir * 128 + 2 * eq] =
                make_float2(rtf32(hv.x), rtf32(hv.y));
        }

        // ---- gate MMA: 4 gate blocks x 8 k-tiles (A-frags loaded per kt) ----
        float cf[4][2];
#pragma unroll
        for (int nt = 0; nt < 4; nt++) { cf[nt][0] = 0.f; cf[nt][1] = 0.f; }
        float dz0 = 0.f, dz1 = 0.f;
#pragma unroll
        for (int kt = 0; kt < 8; kt++) {
            uint32_t a0 = Hrd[gq * HP + kt * 8 + c4];
            uint32_t a2 = Hrd[gq * HP + kt * 8 + c4 + 4];
#pragma unroll
            for (int nt = 0; nt < 4; nt++)
                mma_f16(cf[nt][0], cf[nt][1], dz0, dz1,
                        a0, 0u, a2, 0u, bfrag[nt][kt][0], bfrag[nt][kt][1]);
        }

        // ---- in-register cell update (2 cells), xg from staged smem ----
        {
            float2 xi = *(const float2*)&Xrd[gq * XsP + j0];
            float2 xf = *(const float2*)&Xrd[gq * XsP + 128 + j0];
            float2 xgv = *(const float2*)&Xrd[gq * XsP + 256 + j0];
            float2 xo = *(const float2*)&Xrd[gq * XsP + 384 + j0];
            float h0, h1;
            lstm_cell(cf[0][0] + xi.x, cf[1][0] + xf.x, cf[2][0] + xgv.x, cf[3][0] + xo.x, cr0, h0);
            lstm_cell(cf[0][1] + xi.y, cf[1][1] + xf.y, cf[2][1] + xgv.y, cf[3][1] + xo.y, cr1, h1);
            Hwr[gq * HP + w * 4 + c4] = f2h2(h0, h1);
            if (WRITE_ALL) {
                *(float2*)&Os[(s & 1) * (MR * OsP) + gq * OsP + j0] = make_float2(h0, h1);
            } else if (s == T_SEQ - 1) {
                *(float2*)&out[(row0 + gq) * 256 + j0] = make_float2(h0, h1);
            }
        }
        CP_WAIT0();
        __syncthreads();
    }
    // flush last step's out
    if (WRITE_ALL) {
        const int tp = (dir == 0) ? (T_SEQ - 1) : 0;
        float2 hv = *(const float2*)&Os[((T_SEQ - 1) & 1) * (MR * OsP) + em * OsP + 2 * eq];
        *(float2*)&out[((long)(row0 + em) * T_SEQ + tp) * 256 + dir * 128 + 2 * eq] =
            make_float2(rtf32(hv.x), rtf32(hv.y));
    }
}

// ---------------- layer1 reverse: single step with h0=0 -> pure elementwise ----------------
__global__ void l1rev_kernel() {
    int idx = blockIdx.x * blockDim.x + threadIdx.x;
    if (idx >= 128 * 128) return;
    int b = idx >> 7, j = idx & 127;
    const float* xg = g_xg1r + b * 512;
    float iv = xg[j], gv = xg[256 + j], ov = xg[384 + j];
    float c = sigf(iv) * tanh_fast(gv);
    g_h1last[b * 256 + 128 + j] = sigf(ov) * tanh_fast(c);
}

// ---------------- final FC ----------------
__global__ void fc_kernel(const float* __restrict__ fcw, const float* __restrict__ fcb,
                          float* __restrict__ out) {
    int b = blockIdx.x;
    int lane = threadIdx.x;
    float v[8];
#pragma unroll
    for (int u = 0; u < 8; u++) v[u] = g_h1last[b * 256 + lane + u * 32];
    for (int c = 0; c < 10; c++) {
        float s = 0.f;
#pragma unroll
        for (int u = 0; u < 8; u++) s = fmaf(v[u], fcw[c * 256 + lane + u * 32], s);
#pragma unroll
        for (int o = 16; o; o >>= 1) s += __shfl_xor_sync(0xffffffffu, s, o);
        if (lane == 0) out[b * 10 + c] = s + fcb[c];
    }
}

// ---------------- launch ----------------
extern "C" void kernel_launch(void* const* d_in, const int* in_sizes, int n_in,
                              void* d_out, int out_size) {
    const int*   x        = (const int*)d_in[0];
    const float* emb      = (const float*)d_in[1];
    const float* wih_l0f  = (const float*)d_in[2];
    const float* whh_l0f  = (const float*)d_in[3];
    const float* bih_l0f  = (const float*)d_in[4];
    const float* bhh_l0f  = (const float*)d_in[5];
    const float* wih_l0r  = (const float*)d_in[6];
    const float* whh_l0r  = (const float*)d_in[7];
    const float* bih_l0r  = (const float*)d_in[8];
    const float* bhh_l0r  = (const float*)d_in[9];
    const float* wih_l1f  = (const float*)d_in[10];
    const float* whh_l1f  = (const float*)d_in[11];
    const float* bih_l1f  = (const float*)d_in[12];
    const float* bhh_l1f  = (const float*)d_in[13];
    const float* wih_l1r  = (const float*)d_in[14];
    const float* bih_l1r  = (const float*)d_in[16];
    const float* bhh_l1r  = (const float*)d_in[17];
    const float* fc_w     = (const float*)d_in[18];
    const float* fc_b     = (const float*)d_in[19];
    float* out = (float*)d_out;

    float *pX0, *pWpad, *pW1, *pB0, *pB1f, *pB1r, *pXg0, *pHs0, *pXg1f, *pXg1r, *pH1;
    cudaGetSymbolAddress((void**)&pX0,   g_X0);
    cudaGetSymbolAddress((void**)&pWpad, g_Wpad);
    cudaGetSymbolAddress((void**)&pW1,   g_W1);
    cudaGetSymbolAddress((void**)&pB0,   g_bias0);
    cudaGetSymbolAddress((void**)&pB1f,  g_bias1f);
    cudaGetSymbolAddress((void**)&pB1r,  g_bias1r);
    cudaGetSymbolAddress((void**)&pXg0,  g_xg0);
    cudaGetSymbolAddress((void**)&pHs0,  g_hs0);
    cudaGetSymbolAddress((void**)&pXg1f, g_xg1f);
    cudaGetSymbolAddress((void**)&pXg1r, g_xg1r);
    cudaGetSymbolAddress((void**)&pH1,   g_h1last);

    const int SMEM_SCAN = (2 * MR * HP + 2 * MR * XsP + 2 * MR * OsP) * 4;  // ~46KB

    prep_kernel<<<128, 256>>>(wih_l0f, wih_l0r, wih_l1f,
                              bih_l0f, bhh_l0f, bih_l0r, bhh_l0r,
                              bih_l1f, bhh_l1f, bih_l1r, bhh_l1r);
    embed_kernel<<<2048, 256>>>(x, emb);

    // layer 0 input gates (tensor cores via mma.sync tf32): [65536,304] x [1024,304]^T
    {
        dim3 grid(1024 / 128, MTOT / 128);
        gemm_mma_kernel<<<grid, 256>>>(pX0, KPAD, pWpad, KPAD, pXg0, 1024, KPAD, pB0);
    }
    // layer 0 scan (both dirs): 32 CTAs, fused MMA recurrence, staged IO
    lstm_mma_kernel<2, true><<<32, 512, SMEM_SCAN>>>(pXg0, 1024, whh_l0f, whh_l0r, pHs0);

    // layer 1 forward input gates (tensor cores): [65536,256] x [512,256]^T
    {
        dim3 grid(512 / 128, MTOT / 128);
        gemm_mma_kernel<<<grid, 256>>>(pHs0, 256, pW1, 256, pXg1f, 512, 256, pB1f);
    }
    // layer 1 reverse: only t=T-1 row needed -> tiny GEMM (M=128), fp32 SIMT
    {
        dim3 grid(512 / 64, 1);
        gemm_bias_kernel<<<grid, 256>>>(pHs0 + 511 * 256, T_SEQ * 256, wih_l1r, 256,
                                        pXg1r, 512, 256, pB1r);
    }
    // layer 1 forward scan (only final h needed): 16 CTAs
    lstm_mma_kernel<1, false><<<16, 512, SMEM_SCAN>>>(pXg1f, 512, whh_l1f, whh_l1f, pH1);
    // layer 1 reverse: single step, elementwise
    l1rev_kernel<<<64, 256>>>();

    fc_kernel<<<128, 32>>>(fc_w, fc_b, out);
    (void)in_sizes; (void)n_in; (void)out_size;
}

// round 11
// speedup vs baseline: 1.2781x; 1.0954x over previous
#include <cuda_runtime.h>
#include <cuda_fp16.h>
#include <cstdint>

#define T_SEQ 512
#define B_SZ  128
#define HID   128
#define DEMB  300
#define KPAD  304     // padded to multiple of 16
#define MTOT  65536   // B*T

// single dynamic-smem symbol shared by all dynamic-smem kernels
extern __shared__ char k_smem[];

// ---------------- scratch (device globals; zero-init BSS) ----------------
__device__ float g_X0[MTOT * KPAD];        // padded embedded input, tf32-rounded
__device__ float g_Wpad[1024 * KPAD];      // concat(w_ih_l0f, w_ih_l0r), padded, tf32-rounded
__device__ float g_W1[512 * 256];          // w_ih_l1f, tf32-rounded
__device__ float g_bias0[1024];
__device__ float g_bias1f[512];
__device__ float g_bias1r[512];
__device__ float g_xg0[MTOT * 1024];       // layer0 input gates, both dirs
__device__ float g_hs0[MTOT * 256];        // layer0 output [b][t][fwd128|rev128] (tf32-rounded)
__device__ float g_xg1f[MTOT * 512];
__device__ float g_xg1r[128 * 512];
__device__ float g_h1last[128 * 256];      // [fwd h_T-1 | rev h_at_T-1]
__device__ int   g_cnt0[512];              // [b][tc] ready counters, layer0 gemm
__device__ int   g_cnt1[512];              // layer1 gemm

// ---------------- helpers ----------------
__device__ __forceinline__ float tanhap(float x) {
    float y; asm("tanh.approx.f32 %0, %1;" : "=f"(y) : "f"(x)); return y;
}
__device__ __forceinline__ float sigf(float x) {
    return fmaf(tanhap(0.5f * x), 0.5f, 0.5f);
}
__device__ __forceinline__ float rtf32(float x) {
    uint32_t u;
    asm("cvt.rna.tf32.f32 %0, %1;" : "=r"(u) : "f"(x));
    return __uint_as_float(u);
}
__device__ __forceinline__ uint32_t smem_u32(const void* p) {
    uint32_t a;
    asm("{ .reg .u64 t; cvta.to.shared.u64 t, %1; cvt.u32.u64 %0, t; }" : "=r"(a) : "l"(p));
    return a;
}
__device__ __forceinline__ uint32_t f2h2(float x, float y) {
    __half2 h = __floats2half2_rn(x, y);
    return *reinterpret_cast<uint32_t*>(&h);
}

__device__ __forceinline__ void cp16(void* s, const void* g) {
    uint32_t sa = smem_u32(s);
    asm volatile("cp.async.cg.shared.global [%0], [%1], 16;" :: "r"(sa), "l"(g));
}
#define CP_COMMIT() asm volatile("cp.async.commit_group;" ::: "memory")
#define CP_WAIT0()  asm volatile("cp.async.wait_group 0;" ::: "memory")

__device__ __forceinline__ void mma_tf32(float* c, const uint32_t* a,
                                         uint32_t b0, uint32_t b1) {
    asm volatile(
        "mma.sync.aligned.m16n8k8.row.col.f32.tf32.tf32.f32 "
        "{%0,%1,%2,%3}, {%4,%5,%6,%7}, {%8,%9}, {%0,%1,%2,%3};"
        : "+f"(c[0]), "+f"(c[1]), "+f"(c[2]), "+f"(c[3])
        : "r"(a[0]), "r"(a[1]), "r"(a[2]), "r"(a[3]), "r"(b0), "r"(b1));
}

__device__ __forceinline__ void mma_f16(float& c0, float& c1, float& c2, float& c3,
                                        uint32_t a0, uint32_t a1, uint32_t a2, uint32_t a3,
                                        uint32_t b0, uint32_t b1) {
    asm volatile(
        "mma.sync.aligned.m16n8k16.row.col.f32.f16.f16.f32 "
        "{%0,%1,%2,%3}, {%4,%5,%6,%7}, {%8,%9}, {%0,%1,%2,%3};"
        : "+f"(c0), "+f"(c1), "+f"(c2), "+f"(c3)
        : "r"(a0), "r"(a1), "r"(a2), "r"(a3), "r"(b0), "r"(b1));
}

// LSTM cell via HW tanh: 5 MUFU, no clamps (tanh saturates).
__device__ __forceinline__ void lstm_cell(float gi, float gf, float gg, float go,
                                          float& c, float& h) {
    float iv = sigf(gi), fv = sigf(gf), gv = tanhap(gg), ov = sigf(go);
    c = fmaf(fv, c, iv * gv);
    h = ov * tanhap(c);
}

// ---------------- prep: pad + tf32-round weights, combine biases, zero counters ----------------
__global__ void prep_kernel(const float* __restrict__ wf, const float* __restrict__ wr,
                            const float* __restrict__ w1f,
                            const float* __restrict__ bif, const float* __restrict__ bhf,
                            const float* __restrict__ bir, const float* __restrict__ bhr,
                            const float* __restrict__ b1if, const float* __restrict__ b1hf,
                            const float* __restrict__ b1ir, const float* __restrict__ b1hr) {
    int idx = blockIdx.x * blockDim.x + threadIdx.x;
    int stride = gridDim.x * blockDim.x;
    for (int i = idx; i < 1024 * KPAD; i += stride) {
        int n = i / KPAD, k = i - n * KPAD;
        float v = 0.f;
        if (k < DEMB) v = (n < 512) ? wf[n * DEMB + k] : wr[(n - 512) * DEMB + k];
        g_Wpad[i] = rtf32(v);
    }
    for (int i = idx; i < 512 * 256; i += stride) g_W1[i] = rtf32(w1f[i]);
    if (idx < 1024)
        g_bias0[idx] = (idx < 512) ? (bif[idx] + bhf[idx]) : (bir[idx - 512] + bhr[idx - 512]);
    if (idx < 512) {
        g_bias1f[idx] = b1if[idx] + b1hf[idx];
        g_bias1r[idx] = b1ir[idx] + b1hr[idx];
        g_cnt0[idx] = 0;
        g_cnt1[idx] = 0;
    }
}

// ---------------- embedding gather (tf32-rounded store) ----------------
__global__ void embed_kernel(const int* __restrict__ x, const float* __restrict__ emb) {
    int idx = blockIdx.x * blockDim.x + threadIdx.x;
    int stride = gridDim.x * blockDim.x;
    const int total = MTOT * 75;
    for (int i = idx; i < total; i += stride) {
        int m = i / 75, q = i - m * 75;
        int v = x[m];
        float4 val = *(const float4*)(emb + (long)v * DEMB + q * 4);
        float4 w = make_float4(rtf32(val.x), rtf32(val.y), rtf32(val.z), rtf32(val.w));
        *(float4*)(g_X0 + (long)m * KPAD + q * 4) = w;
    }
}

// ---------------- fp32 tiled GEMM (tiny layer-1 reverse GEMM only) ----------------
__global__ __launch_bounds__(256) void gemm_bias_kernel(
    const float* __restrict__ A, int lda,
    const float* __restrict__ B, int ldb,
    float* __restrict__ C, int ldc,
    int K, const float* __restrict__ bias) {
    __shared__ float As[16][132];
    __shared__ float Bs[16][68];

    const int tid = threadIdx.x;
    const int bm = blockIdx.y * 128, bn = blockIdx.x * 64;
    const int tx = tid & 15, ty = tid >> 4;
    const int arow = tid >> 2, acol = tid & 3;

    float acc[8][4];
#pragma unroll
    for (int i = 0; i < 8; i++)
#pragma unroll
        for (int j = 0; j < 4; j++) acc[i][j] = 0.f;

    const float* Aptr = A + (long)(bm + arow) * lda + acol * 4;
    const float* Bptr = B + (long)(bn + arow) * ldb + acol * 4;

    for (int k0 = 0; k0 < K; k0 += 16) {
        float4 a0 = *(const float4*)(Aptr + k0);
        float4 a1 = *(const float4*)(Aptr + (long)64 * lda + k0);
        float4 b0 = *(const float4*)(Bptr + k0);
        __syncthreads();
        As[acol * 4 + 0][arow] = a0.x; As[acol * 4 + 1][arow] = a0.y;
        As[acol * 4 + 2][arow] = a0.z; As[acol * 4 + 3][arow] = a0.w;
        As[acol * 4 + 0][arow + 64] = a1.x; As[acol * 4 + 1][arow + 64] = a1.y;
        As[acol * 4 + 2][arow + 64] = a1.z; As[acol * 4 + 3][arow + 64] = a1.w;
        Bs[acol * 4 + 0][arow] = b0.x; Bs[acol * 4 + 1][arow] = b0.y;
        Bs[acol * 4 + 2][arow] = b0.z; Bs[acol * 4 + 3][arow] = b0.w;
        __syncthreads();
#pragma unroll
        for (int k = 0; k < 16; k++) {
            float4 av0 = *(float4*)&As[k][ty * 8];
            float4 av1 = *(float4*)&As[k][ty * 8 + 4];
            float4 bv  = *(float4*)&Bs[k][tx * 4];
            float a[8] = {av0.x, av0.y, av0.z, av0.w, av1.x, av1.y, av1.z, av1.w};
            float b[4] = {bv.x, bv.y, bv.z, bv.w};
#pragma unroll
            for (int i = 0; i < 8; i++)
#pragma unroll
                for (int j = 0; j < 4; j++) acc[i][j] = fmaf(a[i], b[j], acc[i][j]);
        }
    }
    float4 bb = *(const float4*)(bias + bn + tx * 4);
#pragma unroll
    for (int i = 0; i < 8; i++) {
        float4 o;
        o.x = acc[i][0] + bb.x; o.y = acc[i][1] + bb.y;
        o.z = acc[i][2] + bb.z; o.w = acc[i][3] + bb.w;
        *(float4*)(C + (long)(bm + ty * 8 + i) * ldc + bn + tx * 4) = o;
    }
}

// ================= fused persistent kernel: tf32 GEMM producer + LSTM scan consumer ==========
// grid = 148, block = 512, 1 CTA/SM (co-resident). CTAs [0,nscan): scan; rest: GEMM.
// GEMM: BM=128 x BN=256 tf32 tiles over (b, t-chunk, n-tile); t-chunk order {0,3,1,2};
// per-(b,tc) counter bumped when all nNt n-tiles done. Scan waits counters per 128-step chunk.
#define MR   8
#define HP   68    // H fp16x2 row stride
#define XsP  516   // Xs fp32 row stride
#define OsP  132   // Os fp32 row stride
#define PAD_K 20
#define G_ASZ (128 * PAD_K)
#define G_BSZ (256 * PAD_K)

template <int NDIR, bool WRITE_ALL>
__global__ __launch_bounds__(512, 1)
void fused_kernel(int nscan,
                  const float* __restrict__ Agm, int Ka,
                  const float* __restrict__ Bw,
                  float* __restrict__ Cgm, int ldc, int nNt,
                  const float* __restrict__ bias,
                  int* __restrict__ cnt,
                  const float* __restrict__ whh_f, const float* __restrict__ whh_r,
                  float* __restrict__ out) {
    const int tid = threadIdx.x;

    if ((int)blockIdx.x >= nscan) {
        // ======================= GEMM producer role =======================
        float* As = (float*)k_smem;                 // [2][G_ASZ]
        float* Bs = (float*)k_smem + 2 * G_ASZ;     // [2][G_BSZ]
        const int lane = tid & 31, w = tid >> 5;
        const int wm = w >> 2, wn = w & 3;          // 4 x 4 warp grid
        const int g = lane >> 2, t = lane & 3;
        const int gid = blockIdx.x - nscan;
        const int ngemm = gridDim.x - nscan;
        const int ntiles = 512 * nNt;               // 128 b x 4 tc x nNt
        const int nit = Ka / 16;
        const int tcmap[4] = {0, 3, 1, 2};

        for (int tau = gid; tau < ntiles; tau += ngemm) {
            const int tcseq = tau / (128 * nNt);
            const int tc = tcmap[tcseq];
            const int rem = tau - tcseq * (128 * nNt);
            const int b = rem / nNt, nti = rem - b * nNt;
            const int bm = b * 512 + tc * 128;
            const int bn = nti * 256;

            float c[2][8][4];
#pragma unroll
            for (int mt = 0; mt < 2; mt++)
#pragma unroll
                for (int nt = 0; nt < 8; nt++)
#pragma unroll
                    for (int j = 0; j < 4; j++) c[mt][nt][j] = 0.f;

            auto load_stage = [&](int it, int p) {
                {   // A: 512 chunks, 1/thread
                    int r = tid >> 2, q = tid & 3;
                    cp16(&As[p * G_ASZ + r * PAD_K + q * 4],
                         Agm + (long)(bm + r) * Ka + it * 16 + q * 4);
                }
#pragma unroll
                for (int i = tid; i < 1024; i += 512) {  // B: 1024 chunks, 2/thread
                    int r = i >> 2, q = i & 3;
                    cp16(&Bs[p * G_BSZ + r * PAD_K + q * 4],
                         Bw + (long)(bn + r) * Ka + it * 16 + q * 4);
                }
                CP_COMMIT();
            };

            load_stage(0, 0);
            for (int it = 0; it < nit; it++) {
                CP_WAIT0();
                __syncthreads();
                if (it + 1 < nit) load_stage(it + 1, (it + 1) & 1);
                const int p = it & 1;
                const float* Ab = As + p * G_ASZ + (wm * 32) * PAD_K;
                const float* Bb = Bs + p * G_BSZ + (wn * 64) * PAD_K;
#pragma unroll
                for (int ks = 0; ks < 2; ks++) {
                    const int k0 = ks * 8;
                    uint32_t afr[2][4];
#pragma unroll
                    for (int mt = 0; mt < 2; mt++) {
                        const float* r0 = Ab + (mt * 16 + g) * PAD_K + k0 + t;
                        const float* r1 = r0 + 8 * PAD_K;
                        afr[mt][0] = __float_as_uint(r0[0]);
                        afr[mt][1] = __float_as_uint(r1[0]);
                        afr[mt][2] = __float_as_uint(r0[4]);
                        afr[mt][3] = __float_as_uint(r1[4]);
                    }
#pragma unroll
                    for (int nt = 0; nt < 8; nt++) {
                        const float* br = Bb + (nt * 8 + g) * PAD_K + k0 + t;
                        uint32_t b0 = __float_as_uint(br[0]);
                        uint32_t b1 = __float_as_uint(br[4]);
                        mma_tf32(c[0][nt], afr[0], b0, b1);
                        mma_tf32(c[1][nt], afr[1], b0, b1);
                    }
                }
                __syncthreads();
            }
#pragma unroll
            for (int mt = 0; mt < 2; mt++) {
                const int row = bm + wm * 32 + mt * 16 + g;
#pragma unroll
                for (int nt = 0; nt < 8; nt++) {
                    const int col = bn + wn * 64 + nt * 8 + 2 * t;
                    float2 bb = *(const float2*)(bias + col);
                    *(float2*)(Cgm + (long)row * ldc + col) =
                        make_float2(c[mt][nt][0] + bb.x, c[mt][nt][1] + bb.y);
                    *(float2*)(Cgm + (long)(row + 8) * ldc + col) =
                        make_float2(c[mt][nt][2] + bb.x, c[mt][nt][3] + bb.y);
                }
            }
            __threadfence();
            __syncthreads();
            if (tid == 0) atomicAdd(&cnt[b * 4 + tc], 1);
        }
        return;
    }

    // ======================= scan consumer role =======================
    uint32_t* Hsh2 = (uint32_t*)k_smem;                  // [2][MR][HP] fp16x2
    float* Xs = (float*)k_smem + 2 * MR * HP;            // [2][MR][XsP]
    float* Os = Xs + 2 * MR * XsP;                       // [2][MR][OsP]

    const int lane = tid & 31, w = tid >> 5;
    const int gq = lane >> 2, c4 = lane & 3;
    int dir, chunk;
    if (NDIR == 2) { dir = blockIdx.x & 1; chunk = blockIdx.x >> 1; }
    else           { dir = 0;              chunk = blockIdx.x; }
    const int row0 = chunk * MR;
    const float* whh = (dir == 0) ? whh_f : whh_r;
    const int goff = (NDIR == 2) ? dir * 512 : 0;
    const float* xg = Cgm;
    const int gst = ldc;

    auto wait_chunk = [&](int tc) {
        if (tid < MR) {
            volatile int* p = cnt + (row0 + tid) * 4 + tc;
            while (*p < nNt) __nanosleep(200);
            __threadfence();
        }
        __syncthreads();
    };

    // pack w_hh B-fragments (fp16), once; nt indexes the GATE block
    uint32_t bfrag[4][8][2];
#pragma unroll
    for (int nt = 0; nt < 4; nt++) {
        const int n = nt * 128 + w * 8 + gq;
        const float* wp = whh + n * 128;
#pragma unroll
        for (int kt = 0; kt < 8; kt++) {
            float2 v0 = *(const float2*)(wp + kt * 16 + 2 * c4);
            float2 v1 = *(const float2*)(wp + kt * 16 + 2 * c4 + 8);
            bfrag[nt][kt][0] = f2h2(v0.x, v0.y);
            bfrag[nt][kt][1] = f2h2(v1.x, v1.y);
        }
    }
    for (int i = tid; i < MR * HP; i += 512) Hsh2[i] = 0;

    const int hr0 = (2 * tid) >> 7, hc0 = ((2 * tid) & 127) * 4;
    const int hr1 = (2 * tid + 1) >> 7, hc1 = ((2 * tid + 1) & 127) * 4;
    const int em = tid >> 6, eq = tid & 63;

    // wait for first chunk, then prefetch xg step 0
    wait_chunk((dir == 0) ? 0 : 3);
    {
        const int t0 = (dir == 0) ? 0 : (T_SEQ - 1);
        cp16(&Xs[hr0 * XsP + hc0],
             xg + ((long)(row0 + hr0) * T_SEQ + t0) * gst + goff + hc0);
        cp16(&Xs[hr1 * XsP + hc1],
             xg + ((long)(row0 + hr1) * T_SEQ + t0) * gst + goff + hc1);
        CP_COMMIT(); CP_WAIT0();
    }
    __syncthreads();

    const int j0 = w * 8 + 2 * c4;
    float cr0 = 0.f, cr1 = 0.f;

    for (int s = 0; s < T_SEQ; s++) {
        const int t = (dir == 0) ? s : (T_SEQ - 1 - s);
        const uint32_t* Hrd = Hsh2 + (s & 1) * (MR * HP);
        uint32_t* Hwr = Hsh2 + ((s + 1) & 1) * (MR * HP);
        const float* Xrd = Xs + (s & 1) * (MR * XsP);
        float* Xwr = Xs + ((s + 1) & 1) * (MR * XsP);

        // gate ready-wait before prefetching into the next chunk
        if (s + 1 < T_SEQ && ((s + 1) & 127) == 0)
            wait_chunk((dir == 0) ? ((s + 1) >> 7) : (3 - ((s + 1) >> 7)));

        if (s + 1 < T_SEQ) {
            const int tn = (dir == 0) ? (s + 1) : (T_SEQ - 2 - s);
            cp16(&Xwr[hr0 * XsP + hc0],
                 xg + ((long)(row0 + hr0) * T_SEQ + tn) * gst + goff + hc0);
            cp16(&Xwr[hr1 * XsP + hc1],
                 xg + ((long)(row0 + hr1) * T_SEQ + tn) * gst + goff + hc1);
        }
        CP_COMMIT();

        // coalesced out-write of previous step's h
        if (WRITE_ALL && s > 0) {
            const int tp = (dir == 0) ? (s - 1) : (T_SEQ - s);
            float2 hv = *(const float2*)&Os[((s - 1) & 1) * (MR * OsP) + em * OsP + 2 * eq];
            *(float2*)&out[((long)(row0 + em) * T_SEQ + tp) * 256 + dir * 128 + 2 * eq] =
                make_float2(rtf32(hv.x), rtf32(hv.y));
        }

        // gate MMA: 4 gate blocks x 8 k-tiles
        float cf[4][2];
#pragma unroll
        for (int nt = 0; nt < 4; nt++) { cf[nt][0] = 0.f; cf[nt][1] = 0.f; }
        float dz0 = 0.f, dz1 = 0.f;
#pragma unroll
        for (int kt = 0; kt < 8; kt++) {
            uint32_t a0 = Hrd[gq * HP + kt * 8 + c4];
            uint32_t a2 = Hrd[gq * HP + kt * 8 + c4 + 4];
#pragma unroll
            for (int nt = 0; nt < 4; nt++)
                mma_f16(cf[nt][0], cf[nt][1], dz0, dz1,
                        a0, 0u, a2, 0u, bfrag[nt][kt][0], bfrag[nt][kt][1]);
        }

        // in-register cell update (2 cells), xg from staged smem
        {
            float2 xi = *(const float2*)&Xrd[gq * XsP + j0];
            float2 xf = *(const float2*)&Xrd[gq * XsP + 128 + j0];
            float2 xgv = *(const float2*)&Xrd[gq * XsP + 256 + j0];
            float2 xo = *(const float2*)&Xrd[gq * XsP + 384 + j0];
            float h0, h1;
            lstm_cell(cf[0][0] + xi.x, cf[1][0] + xf.x, cf[2][0] + xgv.x, cf[3][0] + xo.x, cr0, h0);
            lstm_cell(cf[0][1] + xi.y, cf[1][1] + xf.y, cf[2][1] + xgv.y, cf[3][1] + xo.y, cr1, h1);
            Hwr[gq * HP + w * 4 + c4] = f2h2(h0, h1);
            if (WRITE_ALL) {
                *(float2*)&Os[(s & 1) * (MR * OsP) + gq * OsP + j0] = make_float2(h0, h1);
            } else if (s == T_SEQ - 1) {
                *(float2*)&out[(row0 + gq) * 256 + j0] = make_float2(h0, h1);
            }
        }
        CP_WAIT0();
        __syncthreads();
    }
    if (WRITE_ALL) {
        const int tp = (dir == 0) ? (T_SEQ - 1) : 0;
        float2 hv = *(const float2*)&Os[((T_SEQ - 1) & 1) * (MR * OsP) + em * OsP + 2 * eq];
        *(float2*)&out[((long)(row0 + em) * T_SEQ + tp) * 256 + dir * 128 + 2 * eq] =
            make_float2(rtf32(hv.x), rtf32(hv.y));
    }
}

// ---------------- layer1 reverse: single step with h0=0 -> pure elementwise ----------------
__global__ void l1rev_kernel() {
    int idx = blockIdx.x * blockDim.x + threadIdx.x;
    if (idx >= 128 * 128) return;
    int b = idx >> 7, j = idx & 127;
    const float* xg = g_xg1r + b * 512;
    float c = sigf(xg[j]) * tanhap(xg[256 + j]);
    g_h1last[b * 256 + 128 + j] = sigf(xg[384 + j]) * tanhap(c);
}

// ---------------- final FC ----------------
__global__ void fc_kernel(const float* __restrict__ fcw, const float* __restrict__ fcb,
                          float* __restrict__ out) {
    int b = blockIdx.x;
    int lane = threadIdx.x;
    float v[8];
#pragma unroll
    for (int u = 0; u < 8; u++) v[u] = g_h1last[b * 256 + lane + u * 32];
    for (int c = 0; c < 10; c++) {
        float s = 0.f;
#pragma unroll
        for (int u = 0; u < 8; u++) s = fmaf(v[u], fcw[c * 256 + lane + u * 32], s);
#pragma unroll
        for (int o = 16; o; o >>= 1) s += __shfl_xor_sync(0xffffffffu, s, o);
        if (lane == 0) out[b * 10 + c] = s + fcb[c];
    }
}

// ---------------- launch ----------------
extern "C" void kernel_launch(void* const* d_in, const int* in_sizes, int n_in,
                              void* d_out, int out_size) {
    const int*   x        = (const int*)d_in[0];
    const float* emb      = (const float*)d_in[1];
    const float* wih_l0f  = (const float*)d_in[2];
    const float* whh_l0f  = (const float*)d_in[3];
    const float* bih_l0f  = (const float*)d_in[4];
    const float* bhh_l0f  = (const float*)d_in[5];
    const float* wih_l0r  = (const float*)d_in[6];
    const float* whh_l0r  = (const float*)d_in[7];
    const float* bih_l0r  = (const float*)d_in[8];
    const float* bhh_l0r  = (const float*)d_in[9];
    const float* wih_l1f  = (const float*)d_in[10];
    const float* whh_l1f  = (const float*)d_in[11];
    const float* bih_l1f  = (const float*)d_in[12];
    const float* bhh_l1f  = (const float*)d_in[13];
    const float* wih_l1r  = (const float*)d_in[14];
    const float* bih_l1r  = (const float*)d_in[16];
    const float* bhh_l1r  = (const float*)d_in[17];
    const float* fc_w     = (const float*)d_in[18];
    const float* fc_b     = (const float*)d_in[19];
    float* out = (float*)d_out;

    float *pX0, *pWpad, *pW1, *pB0, *pB1f, *pB1r, *pXg0, *pHs0, *pXg1f, *pXg1r, *pH1;
    int *pCnt0, *pCnt1;
    cudaGetSymbolAddress((void**)&pX0,   g_X0);
    cudaGetSymbolAddress((void**)&pWpad, g_Wpad);
    cudaGetSymbolAddress((void**)&pW1,   g_W1);
    cudaGetSymbolAddress((void**)&pB0,   g_bias0);
    cudaGetSymbolAddress((void**)&pB1f,  g_bias1f);
    cudaGetSymbolAddress((void**)&pB1r,  g_bias1r);
    cudaGetSymbolAddress((void**)&pXg0,  g_xg0);
    cudaGetSymbolAddress((void**)&pHs0,  g_hs0);
    cudaGetSymbolAddress((void**)&pXg1f, g_xg1f);
    cudaGetSymbolAddress((void**)&pXg1r, g_xg1r);
    cudaGetSymbolAddress((void**)&pH1,   g_h1last);
    cudaGetSymbolAddress((void**)&pCnt0, g_cnt0);
    cudaGetSymbolAddress((void**)&pCnt1, g_cnt1);

    const int SMEM_FUSED = 2 * (G_ASZ + G_BSZ) * 4;  // 61440 B
    cudaFuncSetAttribute(fused_kernel<2, true>,
                         cudaFuncAttributeMaxDynamicSharedMemorySize, SMEM_FUSED);
    cudaFuncSetAttribute(fused_kernel<1, false>,
                         cudaFuncAttributeMaxDynamicSharedMemorySize, SMEM_FUSED);

    prep_kernel<<<128, 256>>>(wih_l0f, wih_l0r, wih_l1f,
                              bih_l0f, bhh_l0f, bih_l0r, bhh_l0r,
                              bih_l1f, bhh_l1f, bih_l1r, bhh_l1r);
    embed_kernel<<<2048, 256>>>(x, emb);

    // fused layer0: GEMM [65536,304]x[1024,304]^T producer + bi-dir scan consumer
    fused_kernel<2, true><<<148, 512, SMEM_FUSED>>>(
        32, pX0, KPAD, pWpad, pXg0, 1024, 4, pB0, pCnt0,
        whh_l0f, whh_l0r, pHs0);

    // layer 1 reverse: only t=T-1 row needed -> tiny GEMM + 1-step elementwise
    {
        dim3 grid(512 / 64, 1);
        gemm_bias_kernel<<<grid, 256>>>(pHs0 + 511 * 256, T_SEQ * 256, wih_l1r, 256,
                                        pXg1r, 512, 256, pB1r);
    }
    l1rev_kernel<<<64, 256>>>();

    // fused layer1 fwd: GEMM [65536,256]x[512,256]^T producer + fwd scan consumer
    fused_kernel<1, false><<<148, 512, SMEM_FUSED>>>(
        16, pHs0, 256, pW1, pXg1f, 512, 2, pB1f, pCnt1,
        whh_l1f, whh_l1f, pH1);

    fc_kernel<<<128, 32>>>(fc_w, fc_b, out);
    (void)in_sizes; (void)n_in; (void)out_size;
}

// round 12
// speedup vs baseline: 1.4086x; 1.1021x over previous
#include <cuda_runtime.h>
#include <cuda_fp16.h>
#include <cstdint>

#define T_SEQ 512
#define B_SZ  128
#define HID   128
#define DEMB  300
#define KPAD  304     // padded to multiple of 16
#define MTOT  65536   // B*T

// single dynamic-smem symbol shared by all dynamic-smem kernels
extern __shared__ char k_smem[];

// ---------------- scratch (device globals; zero-init BSS) ----------------
__device__ float g_X0[MTOT * KPAD];        // padded embedded input, tf32-rounded
__device__ float g_Wpad[1024 * KPAD];      // concat(w_ih_l0f, w_ih_l0r), padded, tf32-rounded
__device__ float g_W1[512 * 256];          // w_ih_l1f, tf32-rounded
__device__ float g_bias0[1024];
__device__ float g_bias1f[512];
__device__ float g_bias1r[512];
__device__ float g_xg0[MTOT * 1024];       // layer0 input gates, both dirs
__device__ float g_hs0[MTOT * 256];        // layer0 output [b][t][fwd128|rev128] (tf32-rounded)
__device__ float g_xg1f[MTOT * 512];
__device__ float g_xg1r[128 * 512];
__device__ float g_h1last[128 * 256];      // [fwd h_T-1 | rev h_at_T-1]
__device__ int   g_cnt0[512];              // [b][tc] ready counters, layer0 gemm
__device__ int   g_cnt1[512];              // layer1 gemm

// ---------------- helpers ----------------
__device__ __forceinline__ float tanhap(float x) {
    float y; asm("tanh.approx.f32 %0, %1;" : "=f"(y) : "f"(x)); return y;
}
__device__ __forceinline__ float sigf(float x) {
    return fmaf(tanhap(0.5f * x), 0.5f, 0.5f);
}
__device__ __forceinline__ float rtf32(float x) {
    uint32_t u;
    asm("cvt.rna.tf32.f32 %0, %1;" : "=r"(u) : "f"(x));
    return __uint_as_float(u);
}
__device__ __forceinline__ uint32_t smem_u32(const void* p) {
    uint32_t a;
    asm("{ .reg .u64 t; cvta.to.shared.u64 t, %1; cvt.u32.u64 %0, t; }" : "=r"(a) : "l"(p));
    return a;
}
__device__ __forceinline__ uint32_t f2h2(float x, float y) {
    __half2 h = __floats2half2_rn(x, y);
    return *reinterpret_cast<uint32_t*>(&h);
}

__device__ __forceinline__ void cp16(void* s, const void* g) {
    uint32_t sa = smem_u32(s);
    asm volatile("cp.async.cg.shared.global [%0], [%1], 16;" :: "r"(sa), "l"(g));
}
#define CP_COMMIT() asm volatile("cp.async.commit_group;" ::: "memory")
#define CP_WAIT0()  asm volatile("cp.async.wait_group 0;" ::: "memory")

__device__ __forceinline__ void mma_tf32(float* c, const uint32_t* a,
                                         uint32_t b0, uint32_t b1) {
    asm volatile(
        "mma.sync.aligned.m16n8k8.row.col.f32.tf32.tf32.f32 "
        "{%0,%1,%2,%3}, {%4,%5,%6,%7}, {%8,%9}, {%0,%1,%2,%3};"
        : "+f"(c[0]), "+f"(c[1]), "+f"(c[2]), "+f"(c[3])
        : "r"(a[0]), "r"(a[1]), "r"(a[2]), "r"(a[3]), "r"(b0), "r"(b1));
}

__device__ __forceinline__ void mma_f16(float& c0, float& c1, float& c2, float& c3,
                                        uint32_t a0, uint32_t a1, uint32_t a2, uint32_t a3,
                                        uint32_t b0, uint32_t b1) {
    asm volatile(
        "mma.sync.aligned.m16n8k16.row.col.f32.f16.f16.f32 "
        "{%0,%1,%2,%3}, {%4,%5,%6,%7}, {%8,%9}, {%0,%1,%2,%3};"
        : "+f"(c0), "+f"(c1), "+f"(c2), "+f"(c3)
        : "r"(a0), "r"(a1), "r"(a2), "r"(a3), "r"(b0), "r"(b1));
}

// LSTM cell via HW tanh: 5 MUFU, no clamps (tanh saturates).
__device__ __forceinline__ void lstm_cell(float gi, float gf, float gg, float go,
                                          float& c, float& h) {
    float iv = sigf(gi), fv = sigf(gf), gv = tanhap(gg), ov = sigf(go);
    c = fmaf(fv, c, iv * gv);
    h = ov * tanhap(c);
}

// ---------------- prep ----------------
__global__ void prep_kernel(const float* __restrict__ wf, const float* __restrict__ wr,
                            const float* __restrict__ w1f,
                            const float* __restrict__ bif, const float* __restrict__ bhf,
                            const float* __restrict__ bir, const float* __restrict__ bhr,
                            const float* __restrict__ b1if, const float* __restrict__ b1hf,
                            const float* __restrict__ b1ir, const float* __restrict__ b1hr) {
    int idx = blockIdx.x * blockDim.x + threadIdx.x;
    int stride = gridDim.x * blockDim.x;
    for (int i = idx; i < 1024 * KPAD; i += stride) {
        int n = i / KPAD, k = i - n * KPAD;
        float v = 0.f;
        if (k < DEMB) v = (n < 512) ? wf[n * DEMB + k] : wr[(n - 512) * DEMB + k];
        g_Wpad[i] = rtf32(v);
    }
    for (int i = idx; i < 512 * 256; i += stride) g_W1[i] = rtf32(w1f[i]);
    if (idx < 1024)
        g_bias0[idx] = (idx < 512) ? (bif[idx] + bhf[idx]) : (bir[idx - 512] + bhr[idx - 512]);
    if (idx < 512) {
        g_bias1f[idx] = b1if[idx] + b1hf[idx];
        g_bias1r[idx] = b1ir[idx] + b1hr[idx];
        g_cnt0[idx] = 0;
        g_cnt1[idx] = 0;
    }
}

// ---------------- embedding gather ----------------
__global__ void embed_kernel(const int* __restrict__ x, const float* __restrict__ emb) {
    int idx = blockIdx.x * blockDim.x + threadIdx.x;
    int stride = gridDim.x * blockDim.x;
    const int total = MTOT * 75;
    for (int i = idx; i < total; i += stride) {
        int m = i / 75, q = i - m * 75;
        int v = x[m];
        float4 val = *(const float4*)(emb + (long)v * DEMB + q * 4);
        float4 w = make_float4(rtf32(val.x), rtf32(val.y), rtf32(val.z), rtf32(val.w));
        *(float4*)(g_X0 + (long)m * KPAD + q * 4) = w;
    }
}

// ---------------- fp32 tiled GEMM (tiny layer-1 reverse GEMM only) ----------------
__global__ __launch_bounds__(256) void gemm_bias_kernel(
    const float* __restrict__ A, int lda,
    const float* __restrict__ B, int ldb,
    float* __restrict__ C, int ldc,
    int K, const float* __restrict__ bias) {
    __shared__ float As[16][132];
    __shared__ float Bs[16][68];

    const int tid = threadIdx.x;
    const int bm = blockIdx.y * 128, bn = blockIdx.x * 64;
    const int tx = tid & 15, ty = tid >> 4;
    const int arow = tid >> 2, acol = tid & 3;

    float acc[8][4];
#pragma unroll
    for (int i = 0; i < 8; i++)
#pragma unroll
        for (int j = 0; j < 4; j++) acc[i][j] = 0.f;

    const float* Aptr = A + (long)(bm + arow) * lda + acol * 4;
    const float* Bptr = B + (long)(bn + arow) * ldb + acol * 4;

    for (int k0 = 0; k0 < K; k0 += 16) {
        float4 a0 = *(const float4*)(Aptr + k0);
        float4 a1 = *(const float4*)(Aptr + (long)64 * lda + k0);
        float4 b0 = *(const float4*)(Bptr + k0);
        __syncthreads();
        As[acol * 4 + 0][arow] = a0.x; As[acol * 4 + 1][arow] = a0.y;
        As[acol * 4 + 2][arow] = a0.z; As[acol * 4 + 3][arow] = a0.w;
        As[acol * 4 + 0][arow + 64] = a1.x; As[acol * 4 + 1][arow + 64] = a1.y;
        As[acol * 4 + 2][arow + 64] = a1.z; As[acol * 4 + 3][arow + 64] = a1.w;
        Bs[acol * 4 + 0][arow] = b0.x; Bs[acol * 4 + 1][arow] = b0.y;
        Bs[acol * 4 + 2][arow] = b0.z; Bs[acol * 4 + 3][arow] = b0.w;
        __syncthreads();
#pragma unroll
        for (int k = 0; k < 16; k++) {
            float4 av0 = *(float4*)&As[k][ty * 8];
            float4 av1 = *(float4*)&As[k][ty * 8 + 4];
            float4 bv  = *(float4*)&Bs[k][tx * 4];
            float a[8] = {av0.x, av0.y, av0.z, av0.w, av1.x, av1.y, av1.z, av1.w};
            float b[4] = {bv.x, bv.y, bv.z, bv.w};
#pragma unroll
            for (int i = 0; i < 8; i++)
#pragma unroll
                for (int j = 0; j < 4; j++) acc[i][j] = fmaf(a[i], b[j], acc[i][j]);
        }
    }
    float4 bb = *(const float4*)(bias + bn + tx * 4);
#pragma unroll
    for (int i = 0; i < 8; i++) {
        float4 o;
        o.x = acc[i][0] + bb.x; o.y = acc[i][1] + bb.y;
        o.z = acc[i][2] + bb.z; o.w = acc[i][3] + bb.w;
        *(float4*)(C + (long)(bm + ty * 8 + i) * ldc + bn + tx * 4) = o;
    }
}

// ================= fused persistent kernel: tf32 GEMM producer + LSTM scan consumer ==========
#define MR   8
#define HP   68    // H fp16x2 row stride
#define XsP  516   // Xs fp32 row stride
#define PAD_K 20
#define G_ASZ (128 * PAD_K)
#define G_BSZ (256 * PAD_K)

template <int NDIR, bool WRITE_ALL>
__global__ __launch_bounds__(512, 1)
void fused_kernel(int nscan,
                  const float* __restrict__ Agm, int Ka,
                  const float* __restrict__ Bw,
                  float* __restrict__ Cgm, int ldc, int nNt,
                  const float* __restrict__ bias,
                  int* __restrict__ cnt,
                  const float* __restrict__ whh_f, const float* __restrict__ whh_r,
                  float* __restrict__ out) {
    const int tid = threadIdx.x;

    if ((int)blockIdx.x >= nscan) {
        // ======================= GEMM producer role =======================
        float* As = (float*)k_smem;                 // [2][G_ASZ]
        float* Bs = (float*)k_smem + 2 * G_ASZ;     // [2][G_BSZ]
        const int lane = tid & 31, w = tid >> 5;
        const int wm = w >> 2, wn = w & 3;          // 4 x 4 warp grid
        const int g = lane >> 2, t = lane & 3;
        const int gid = blockIdx.x - nscan;
        const int ngemm = gridDim.x - nscan;
        const int ntiles = 512 * nNt;               // 128 b x 4 tc x nNt
        const int nit = Ka / 16;
        const int tcmap[4] = {0, 3, 1, 2};

        for (int tau = gid; tau < ntiles; tau += ngemm) {
            const int tcseq = tau / (128 * nNt);
            const int tc = tcmap[tcseq];
            const int rem = tau - tcseq * (128 * nNt);
            const int b = rem / nNt, nti = rem - b * nNt;
            const int bm = b * 512 + tc * 128;
            const int bn = nti * 256;

            float c[2][8][4];
#pragma unroll
            for (int mt = 0; mt < 2; mt++)
#pragma unroll
                for (int nt = 0; nt < 8; nt++)
#pragma unroll
                    for (int j = 0; j < 4; j++) c[mt][nt][j] = 0.f;

            auto load_stage = [&](int it, int p) {
                {
                    int r = tid >> 2, q = tid & 3;
                    cp16(&As[p * G_ASZ + r * PAD_K + q * 4],
                         Agm + (long)(bm + r) * Ka + it * 16 + q * 4);
                }
#pragma unroll
                for (int i = tid; i < 1024; i += 512) {
                    int r = i >> 2, q = i & 3;
                    cp16(&Bs[p * G_BSZ + r * PAD_K + q * 4],
                         Bw + (long)(bn + r) * Ka + it * 16 + q * 4);
                }
                CP_COMMIT();
            };

            load_stage(0, 0);
            for (int it = 0; it < nit; it++) {
                CP_WAIT0();
                __syncthreads();
                if (it + 1 < nit) load_stage(it + 1, (it + 1) & 1);
                const int p = it & 1;
                const float* Ab = As + p * G_ASZ + (wm * 32) * PAD_K;
                const float* Bb = Bs + p * G_BSZ + (wn * 64) * PAD_K;
#pragma unroll
                for (int ks = 0; ks < 2; ks++) {
                    const int k0 = ks * 8;
                    uint32_t afr[2][4];
#pragma unroll
                    for (int mt = 0; mt < 2; mt++) {
                        const float* r0 = Ab + (mt * 16 + g) * PAD_K + k0 + t;
                        const float* r1 = r0 + 8 * PAD_K;
                        afr[mt][0] = __float_as_uint(r0[0]);
                        afr[mt][1] = __float_as_uint(r1[0]);
                        afr[mt][2] = __float_as_uint(r0[4]);
                        afr[mt][3] = __float_as_uint(r1[4]);
                    }
#pragma unroll
                    for (int nt = 0; nt < 8; nt++) {
                        const float* br = Bb + (nt * 8 + g) * PAD_K + k0 + t;
                        uint32_t b0 = __float_as_uint(br[0]);
                        uint32_t b1 = __float_as_uint(br[4]);
                        mma_tf32(c[0][nt], afr[0], b0, b1);
                        mma_tf32(c[1][nt], afr[1], b0, b1);
                    }
                }
                __syncthreads();
            }
#pragma unroll
            for (int mt = 0; mt < 2; mt++) {
                const int row = bm + wm * 32 + mt * 16 + g;
#pragma unroll
                for (int nt = 0; nt < 8; nt++) {
                    const int col = bn + wn * 64 + nt * 8 + 2 * t;
                    float2 bb = *(const float2*)(bias + col);
                    *(float2*)(Cgm + (long)row * ldc + col) =
                        make_float2(c[mt][nt][0] + bb.x, c[mt][nt][1] + bb.y);
                    *(float2*)(Cgm + (long)(row + 8) * ldc + col) =
                        make_float2(c[mt][nt][2] + bb.x, c[mt][nt][3] + bb.y);
                }
            }
            __threadfence();
            __syncthreads();
            if (tid == 0) atomicAdd(&cnt[b * 4 + tc], 1);
        }
        return;
    }

    // ======================= scan consumer role =======================
    uint32_t* Hsh2 = (uint32_t*)k_smem;                  // [2][MR][HP] fp16x2
    float* Xs = (float*)k_smem + 2 * MR * HP;            // [2][MR][XsP]

    const int lane = tid & 31, w = tid >> 5;
    const int gq = lane >> 2, c4 = lane & 3;
    int dir, chunk;
    if (NDIR == 2) { dir = blockIdx.x & 1; chunk = blockIdx.x >> 1; }
    else           { dir = 0;              chunk = blockIdx.x; }
    const int row0 = chunk * MR;
    const float* whh = (dir == 0) ? whh_f : whh_r;
    const int goff = (NDIR == 2) ? dir * 512 : 0;
    const float* xg = Cgm;
    const int gst = ldc;
    const long sgn = (dir == 0) ? (long)gst : -(long)gst;

    auto wait_chunk = [&](int tc) {
        if (tid < MR) {
            volatile int* p = cnt + (row0 + tid) * 4 + tc;
            while (*p < nNt) __nanosleep(200);
            __threadfence();
        }
        __syncthreads();
    };

    // pack w_hh B-fragments (fp16), once; nt indexes the GATE block
    uint32_t bfrag[4][8][2];
#pragma unroll
    for (int nt = 0; nt < 4; nt++) {
        const int n = nt * 128 + w * 8 + gq;
        const float* wp = whh + n * 128;
#pragma unroll
        for (int kt = 0; kt < 8; kt++) {
            float2 v0 = *(const float2*)(wp + kt * 16 + 2 * c4);
            float2 v1 = *(const float2*)(wp + kt * 16 + 2 * c4 + 8);
            bfrag[nt][kt][0] = f2h2(v0.x, v0.y);
            bfrag[nt][kt][1] = f2h2(v1.x, v1.y);
        }
    }
    for (int i = tid; i < MR * HP; i += 512) Hsh2[i] = 0;

    const int hr0 = (2 * tid) >> 7, hc0 = ((2 * tid) & 127) * 4;
    const int hr1 = (2 * tid + 1) >> 7, hc1 = ((2 * tid + 1) & 127) * 4;
    const int t0 = (dir == 0) ? 0 : (T_SEQ - 1);

    // hoisted, incrementing GMEM pointers
    const float* xp0 = xg + ((long)(row0 + hr0) * T_SEQ + t0) * gst + goff + hc0;
    const float* xp1 = xg + ((long)(row0 + hr1) * T_SEQ + t0) * gst + goff + hc1;
    const int j0 = w * 8 + 2 * c4;
    float* outp = WRITE_ALL
        ? out + ((long)(row0 + gq) * T_SEQ + t0) * 256 + dir * 128 + j0
        : out + (row0 + gq) * 256 + j0;
    const long osgn = (dir == 0) ? 256L : -256L;

    // wait for first chunk, then prefetch xg step 0
    wait_chunk((dir == 0) ? 0 : 3);
    cp16(&Xs[hr0 * XsP + hc0], xp0);
    cp16(&Xs[hr1 * XsP + hc1], xp1);
    CP_COMMIT(); CP_WAIT0();
    __syncthreads();

    float cr0 = 0.f, cr1 = 0.f;

    auto step_body = [&](int s, int pr, int pw) {
        const uint32_t* Hrd = Hsh2 + pr * (MR * HP);
        uint32_t* Hwr = Hsh2 + pw * (MR * HP);
        const float* Xrd = Xs + pr * (MR * XsP);
        float* Xwr = Xs + pw * (MR * XsP);

        if (s + 1 < T_SEQ && ((s + 1) & 127) == 0)
            wait_chunk((dir == 0) ? ((s + 1) >> 7) : (3 - ((s + 1) >> 7)));

        if (s + 1 < T_SEQ) {
            xp0 += sgn; xp1 += sgn;
            cp16(&Xwr[hr0 * XsP + hc0], xp0);
            cp16(&Xwr[hr1 * XsP + hc1], xp1);
        }
        CP_COMMIT();

        // gate MMA: 4 gate blocks x 8 k-tiles
        float cf[4][2];
#pragma unroll
        for (int nt = 0; nt < 4; nt++) { cf[nt][0] = 0.f; cf[nt][1] = 0.f; }
        float dz0 = 0.f, dz1 = 0.f;
#pragma unroll
        for (int kt = 0; kt < 8; kt++) {
            uint32_t a0 = Hrd[gq * HP + kt * 8 + c4];
            uint32_t a2 = Hrd[gq * HP + kt * 8 + c4 + 4];
#pragma unroll
            for (int nt = 0; nt < 4; nt++)
                mma_f16(cf[nt][0], cf[nt][1], dz0, dz1,
                        a0, 0u, a2, 0u, bfrag[nt][kt][0], bfrag[nt][kt][1]);
        }

        // in-register cell update (2 cells), xg from staged smem; direct h store
        float2 xi = *(const float2*)&Xrd[gq * XsP + j0];
        float2 xf = *(const float2*)&Xrd[gq * XsP + 128 + j0];
        float2 xgv = *(const float2*)&Xrd[gq * XsP + 256 + j0];
        float2 xo = *(const float2*)&Xrd[gq * XsP + 384 + j0];
        float h0, h1;
        lstm_cell(cf[0][0] + xi.x, cf[1][0] + xf.x, cf[2][0] + xgv.x, cf[3][0] + xo.x, cr0, h0);
        lstm_cell(cf[0][1] + xi.y, cf[1][1] + xf.y, cf[2][1] + xgv.y, cf[3][1] + xo.y, cr1, h1);
        Hwr[gq * HP + w * 4 + c4] = f2h2(h0, h1);
        if (WRITE_ALL) {
            *(float2*)outp = make_float2(rtf32(h0), rtf32(h1));
            outp += osgn;
        } else if (s == T_SEQ - 1) {
            *(float2*)outp = make_float2(h0, h1);
        }
        CP_WAIT0();
        __syncthreads();
    };

    for (int s = 0; s < T_SEQ; s += 2) {
        step_body(s, 0, 1);
        step_body(s + 1, 1, 0);
    }
}

// ---------------- layer1 reverse: single step with h0=0 -> pure elementwise ----------------
__global__ void l1rev_kernel() {
    int idx = blockIdx.x * blockDim.x + threadIdx.x;
    if (idx >= 128 * 128) return;
    int b = idx >> 7, j = idx & 127;
    const float* xg = g_xg1r + b * 512;
    float c = sigf(xg[j]) * tanhap(xg[256 + j]);
    g_h1last[b * 256 + 128 + j] = sigf(xg[384 + j]) * tanhap(c);
}

// ---------------- final FC ----------------
__global__ void fc_kernel(const float* __restrict__ fcw, const float* __restrict__ fcb,
                          float* __restrict__ out) {
    int b = blockIdx.x;
    int lane = threadIdx.x;
    float v[8];
#pragma unroll
    for (int u = 0; u < 8; u++) v[u] = g_h1last[b * 256 + lane + u * 32];
    for (int c = 0; c < 10; c++) {
        float s = 0.f;
#pragma unroll
        for (int u = 0; u < 8; u++) s = fmaf(v[u], fcw[c * 256 + lane + u * 32], s);
#pragma unroll
        for (int o = 16; o; o >>= 1) s += __shfl_xor_sync(0xffffffffu, s, o);
        if (lane == 0) out[b * 10 + c] = s + fcb[c];
    }
}

// ---------------- launch ----------------
extern "C" void kernel_launch(void* const* d_in, const int* in_sizes, int n_in,
                              void* d_out, int out_size) {
    const int*   x        = (const int*)d_in[0];
    const float* emb      = (const float*)d_in[1];
    const float* wih_l0f  = (const float*)d_in[2];
    const float* whh_l0f  = (const float*)d_in[3];
    const float* bih_l0f  = (const float*)d_in[4];
    const float* bhh_l0f  = (const float*)d_in[5];
    const float* wih_l0r  = (const float*)d_in[6];
    const float* whh_l0r  = (const float*)d_in[7];
    const float* bih_l0r  = (const float*)d_in[8];
    const float* bhh_l0r  = (const float*)d_in[9];
    const float* wih_l1f  = (const float*)d_in[10];
    const float* whh_l1f  = (const float*)d_in[11];
    const float* bih_l1f  = (const float*)d_in[12];
    const float* bhh_l1f  = (const float*)d_in[13];
    const float* wih_l1r  = (const float*)d_in[14];
    const float* bih_l1r  = (const float*)d_in[16];
    const float* bhh_l1r  = (const float*)d_in[17];
    const float* fc_w     = (const float*)d_in[18];
    const float* fc_b     = (const float*)d_in[19];
    float* out = (float*)d_out;

    float *pX0, *pWpad, *pW1, *pB0, *pB1f, *pB1r, *pXg0, *pHs0, *pXg1f, *pXg1r, *pH1;
    int *pCnt0, *pCnt1;
    cudaGetSymbolAddress((void**)&pX0,   g_X0);
    cudaGetSymbolAddress((void**)&pWpad, g_Wpad);
    cudaGetSymbolAddress((void**)&pW1,   g_W1);
    cudaGetSymbolAddress((void**)&pB0,   g_bias0);
    cudaGetSymbolAddress((void**)&pB1f,  g_bias1f);
    cudaGetSymbolAddress((void**)&pB1r,  g_bias1r);
    cudaGetSymbolAddress((void**)&pXg0,  g_xg0);
    cudaGetSymbolAddress((void**)&pHs0,  g_hs0);
    cudaGetSymbolAddress((void**)&pXg1f, g_xg1f);
    cudaGetSymbolAddress((void**)&pXg1r, g_xg1r);
    cudaGetSymbolAddress((void**)&pH1,   g_h1last);
    cudaGetSymbolAddress((void**)&pCnt0, g_cnt0);
    cudaGetSymbolAddress((void**)&pCnt1, g_cnt1);

    const int SMEM_FUSED = 2 * (G_ASZ + G_BSZ) * 4;  // 61440 B
    cudaFuncSetAttribute(fused_kernel<2, true>,
                         cudaFuncAttributeMaxDynamicSharedMemorySize, SMEM_FUSED);
    cudaFuncSetAttribute(fused_kernel<1, false>,
                         cudaFuncAttributeMaxDynamicSharedMemorySize, SMEM_FUSED);

    prep_kernel<<<128, 256>>>(wih_l0f, wih_l0r, wih_l1f,
                              bih_l0f, bhh_l0f, bih_l0r, bhh_l0r,
                              bih_l1f, bhh_l1f, bih_l1r, bhh_l1r);
    embed_kernel<<<2048, 256>>>(x, emb);

    // fused layer0: GEMM [65536,304]x[1024,304]^T producer + bi-dir scan consumer
    fused_kernel<2, true><<<148, 512, SMEM_FUSED>>>(
        32, pX0, KPAD, pWpad, pXg0, 1024, 4, pB0, pCnt0,
        whh_l0f, whh_l0r, pHs0);

    // layer 1 reverse: only t=T-1 row needed -> tiny GEMM + 1-step elementwise
    {
        dim3 grid(512 / 64, 1);
        gemm_bias_kernel<<<grid, 256>>>(pHs0 + 511 * 256, T_SEQ * 256, wih_l1r, 256,
                                        pXg1r, 512, 256, pB1r);
    }
    l1rev_kernel<<<64, 256>>>();

    // fused layer1 fwd: GEMM [65536,256]x[512,256]^T producer + fwd scan consumer
    fused_kernel<1, false><<<148, 512, SMEM_FUSED>>>(
        16, pHs0, 256, pW1, pXg1f, 512, 2, pB1f, pCnt1,
        whh_l1f, whh_l1f, pH1);

    fc_kernel<<<128, 32>>>(fc_w, fc_b, out);
    (void)in_sizes; (void)n_in; (void)out_size;
}

// round 14
// speedup vs baseline: 1.4265x; 1.0127x over previous
#include <cuda_runtime.h>
#include <cuda_fp16.h>
#include <cstdint>

#define T_SEQ 512
#define B_SZ  128
#define HID   128
#define DEMB  300
#define KPAD  304     // padded to multiple of 16
#define MTOT  65536   // B*T

// single dynamic-smem symbol shared by all dynamic-smem kernels
extern __shared__ char k_smem[];

// ---------------- scratch (device globals; zero-init BSS) ----------------
__device__ float g_X0[MTOT * KPAD];        // padded embedded input, tf32-rounded
__device__ float g_Wpad[1024 * KPAD];      // concat(w_ih_l0f, w_ih_l0r), padded, tf32-rounded
__device__ float g_W1[512 * 256];          // w_ih_l1f, tf32-rounded
__device__ float g_bias0[1024];
__device__ float g_bias1f[512];
__device__ float g_bias1r[512];
__device__ float g_xg0[MTOT * 1024];       // layer0 input gates, both dirs
__device__ float g_hs0[MTOT * 256];        // layer0 output [b][t][fwd128|rev128] (tf32-rounded)
__device__ float g_xg1f[MTOT * 512];
__device__ float g_xg1r[128 * 512];
__device__ float g_h1last[128 * 256];      // [fwd h_T-1 | rev h_at_T-1]
__device__ int   g_cnt0[512];              // [b][tc] ready counters, layer0 gemm
__device__ int   g_cnt1[512];              // layer1 gemm

// ---------------- helpers ----------------
__device__ __forceinline__ float tanhap(float x) {
    float y; asm("tanh.approx.f32 %0, %1;" : "=f"(y) : "f"(x)); return y;
}
__device__ __forceinline__ float sigf(float x) {
    return fmaf(tanhap(0.5f * x), 0.5f, 0.5f);
}
__device__ __forceinline__ float rtf32(float x) {
    uint32_t u;
    asm("cvt.rna.tf32.f32 %0, %1;" : "=r"(u) : "f"(x));
    return __uint_as_float(u);
}
__device__ __forceinline__ uint32_t smem_u32(const void* p) {
    uint32_t a;
    asm("{ .reg .u64 t; cvta.to.shared.u64 t, %1; cvt.u32.u64 %0, t; }" : "=r"(a) : "l"(p));
    return a;
}
__device__ __forceinline__ uint32_t f2h2(float x, float y) {
    __half2 h = __floats2half2_rn(x, y);
    return *reinterpret_cast<uint32_t*>(&h);
}

__device__ __forceinline__ void cp16(void* s, const void* g) {
    uint32_t sa = smem_u32(s);
    asm volatile("cp.async.cg.shared.global [%0], [%1], 16;" :: "r"(sa), "l"(g));
}
#define CP_COMMIT() asm volatile("cp.async.commit_group;" ::: "memory")
#define CP_WAIT0()  asm volatile("cp.async.wait_group 0;" ::: "memory")
#define CP_WAIT1()  asm volatile("cp.async.wait_group 1;" ::: "memory")

__device__ __forceinline__ void mma_tf32(float* c, const uint32_t* a,
                                         uint32_t b0, uint32_t b1) {
    asm volatile(
        "mma.sync.aligned.m16n8k8.row.col.f32.tf32.tf32.f32 "
        "{%0,%1,%2,%3}, {%4,%5,%6,%7}, {%8,%9}, {%0,%1,%2,%3};"
        : "+f"(c[0]), "+f"(c[1]), "+f"(c[2]), "+f"(c[3])
        : "r"(a[0]), "r"(a[1]), "r"(a[2]), "r"(a[3]), "r"(b0), "r"(b1));
}

__device__ __forceinline__ void mma_f16(float& c0, float& c1, float& c2, float& c3,
                                        uint32_t a0, uint32_t a1, uint32_t a2, uint32_t a3,
                                        uint32_t b0, uint32_t b1) {
    asm volatile(
        "mma.sync.aligned.m16n8k16.row.col.f32.f16.f16.f32 "
        "{%0,%1,%2,%3}, {%4,%5,%6,%7}, {%8,%9}, {%0,%1,%2,%3};"
        : "+f"(c0), "+f"(c1), "+f"(c2), "+f"(c3)
        : "r"(a0), "r"(a1), "r"(a2), "r"(a3), "r"(b0), "r"(b1));
}

// LSTM cell via HW tanh: 5 MUFU, no clamps (tanh saturates).
__device__ __forceinline__ void lstm_cell(float gi, float gf, float gg, float go,
                                          float& c, float& h) {
    float iv = sigf(gi), fv = sigf(gf), gv = tanhap(gg), ov = sigf(go);
    c = fmaf(fv, c, iv * gv);
    h = ov * tanhap(c);
}

// ---------------- prep ----------------
__global__ void prep_kernel(const float* __restrict__ wf, const float* __restrict__ wr,
                            const float* __restrict__ w1f,
                            const float* __restrict__ bif, const float* __restrict__ bhf,
                            const float* __restrict__ bir, const float* __restrict__ bhr,
                            const float* __restrict__ b1if, const float* __restrict__ b1hf,
                            const float* __restrict__ b1ir, const float* __restrict__ b1hr) {
    int idx = blockIdx.x * blockDim.x + threadIdx.x;
    int stride = gridDim.x * blockDim.x;
    for (int i = idx; i < 1024 * KPAD; i += stride) {
        int n = i / KPAD, k = i - n * KPAD;
        float v = 0.f;
        if (k < DEMB) v = (n < 512) ? wf[n * DEMB + k] : wr[(n - 512) * DEMB + k];
        g_Wpad[i] = rtf32(v);
    }
    for (int i = idx; i < 512 * 256; i += stride) g_W1[i] = rtf32(w1f[i]);
    if (idx < 1024)
        g_bias0[idx] = (idx < 512) ? (bif[idx] + bhf[idx]) : (bir[idx - 512] + bhr[idx - 512]);
    if (idx < 512) {
        g_bias1f[idx] = b1if[idx] + b1hf[idx];
        g_bias1r[idx] = b1ir[idx] + b1hr[idx];
        g_cnt0[idx] = 0;
        g_cnt1[idx] = 0;
    }
}

// ---------------- embedding gather ----------------
__global__ void embed_kernel(const int* __restrict__ x, const float* __restrict__ emb) {
    int idx = blockIdx.x * blockDim.x + threadIdx.x;
    int stride = gridDim.x * blockDim.x;
    const int total = MTOT * 75;
    for (int i = idx; i < total; i += stride) {
        int m = i / 75, q = i - m * 75;
        int v = x[m];
        float4 val = *(const float4*)(emb + (long)v * DEMB + q * 4);
        float4 w = make_float4(rtf32(val.x), rtf32(val.y), rtf32(val.z), rtf32(val.w));
        *(float4*)(g_X0 + (long)m * KPAD + q * 4) = w;
    }
}

// ---------------- fp32 tiled GEMM (tiny layer-1 reverse GEMM only) ----------------
__global__ __launch_bounds__(256) void gemm_bias_kernel(
    const float* __restrict__ A, int lda,
    const float* __restrict__ B, int ldb,
    float* __restrict__ C, int ldc,
    int K, const float* __restrict__ bias) {
    __shared__ float As[16][132];
    __shared__ float Bs[16][68];

    const int tid = threadIdx.x;
    const int bm = blockIdx.y * 128, bn = blockIdx.x * 64;
    const int tx = tid & 15, ty = tid >> 4;
    const int arow = tid >> 2, acol = tid & 3;

    float acc[8][4];
#pragma unroll
    for (int i = 0; i < 8; i++)
#pragma unroll
        for (int j = 0; j < 4; j++) acc[i][j] = 0.f;

    const float* Aptr = A + (long)(bm + arow) * lda + acol * 4;
    const float* Bptr = B + (long)(bn + arow) * ldb + acol * 4;

    for (int k0 = 0; k0 < K; k0 += 16) {
        float4 a0 = *(const float4*)(Aptr + k0);
        float4 a1 = *(const float4*)(Aptr + (long)64 * lda + k0);
        float4 b0 = *(const float4*)(Bptr + k0);
        __syncthreads();
        As[acol * 4 + 0][arow] = a0.x; As[acol * 4 + 1][arow] = a0.y;
        As[acol * 4 + 2][arow] = a0.z; As[acol * 4 + 3][arow] = a0.w;
        As[acol * 4 + 0][arow + 64] = a1.x; As[acol * 4 + 1][arow + 64] = a1.y;
        As[acol * 4 + 2][arow + 64] = a1.z; As[acol * 4 + 3][arow + 64] = a1.w;
        Bs[acol * 4 + 0][arow] = b0.x; Bs[acol * 4 + 1][arow] = b0.y;
        Bs[acol * 4 + 2][arow] = b0.z; Bs[acol * 4 + 3][arow] = b0.w;
        __syncthreads();
#pragma unroll
        for (int k = 0; k < 16; k++) {
            float4 av0 = *(float4*)&As[k][ty * 8];
            float4 av1 = *(float4*)&As[k][ty * 8 + 4];
            float4 bv  = *(float4*)&Bs[k][tx * 4];
            float a[8] = {av0.x, av0.y, av0.z, av0.w, av1.x, av1.y, av1.z, av1.w};
            float b[4] = {bv.x, bv.y, bv.z, bv.w};
#pragma unroll
            for (int i = 0; i < 8; i++)
#pragma unroll
                for (int j = 0; j < 4; j++) acc[i][j] = fmaf(a[i], b[j], acc[i][j]);
        }
    }
    float4 bb = *(const float4*)(bias + bn + tx * 4);
#pragma unroll
    for (int i = 0; i < 8; i++) {
        float4 o;
        o.x = acc[i][0] + bb.x; o.y = acc[i][1] + bb.y;
        o.z = acc[i][2] + bb.z; o.w = acc[i][3] + bb.w;
        *(float4*)(C + (long)(bm + ty * 8 + i) * ldc + bn + tx * 4) = o;
    }
}

// ================= fused persistent kernel: tf32 GEMM producer + LSTM scan consumer ==========
#define MR   8
#define HP   68    // H fp16x2 row stride
#define XsP  516   // Xs fp32 row stride
#define PAD_K 20
#define G_ASZ (128 * PAD_K)
#define G_BSZ (256 * PAD_K)

template <int NDIR, bool WRITE_ALL>
__global__ __launch_bounds__(512, 1)
void fused_kernel(int nscan,
                  const float* __restrict__ Agm, int Ka,
                  const float* __restrict__ Bw,
                  float* __restrict__ Cgm, int ldc, int nNt,
                  const float* __restrict__ bias,
                  int* __restrict__ cnt,
                  const float* __restrict__ whh_f, const float* __restrict__ whh_r,
                  float* __restrict__ out) {
    const int tid = threadIdx.x;

    if ((int)blockIdx.x >= nscan) {
        // ======================= GEMM producer role =======================
        float* As = (float*)k_smem;                 // [2][G_ASZ]
        float* Bs = (float*)k_smem + 2 * G_ASZ;     // [2][G_BSZ]
        const int lane = tid & 31, w = tid >> 5;
        const int wm = w >> 2, wn = w & 3;          // 4 x 4 warp grid
        const int g = lane >> 2, t = lane & 3;
        const int gid = blockIdx.x - nscan;
        const int ngemm = gridDim.x - nscan;
        const int ntiles = 512 * nNt;               // 128 b x 4 tc x nNt
        const int nit = Ka / 16;
        const int tcmap[4] = {0, 3, 1, 2};

        for (int tau = gid; tau < ntiles; tau += ngemm) {
            const int tcseq = tau / (128 * nNt);
            const int tc = tcmap[tcseq];
            const int rem = tau - tcseq * (128 * nNt);
            const int b = rem / nNt, nti = rem - b * nNt;
            const int bm = b * 512 + tc * 128;
            const int bn = nti * 256;

            float c[2][8][4];
#pragma unroll
            for (int mt = 0; mt < 2; mt++)
#pragma unroll
                for (int nt = 0; nt < 8; nt++)
#pragma unroll
                    for (int j = 0; j < 4; j++) c[mt][nt][j] = 0.f;

            auto load_stage = [&](int it, int p) {
                {
                    int r = tid >> 2, q = tid & 3;
                    cp16(&As[p * G_ASZ + r * PAD_K + q * 4],
                         Agm + (long)(bm + r) * Ka + it * 16 + q * 4);
                }
#pragma unroll
                for (int i = tid; i < 1024; i += 512) {
                    int r = i >> 2, q = i & 3;
                    cp16(&Bs[p * G_BSZ + r * PAD_K + q * 4],
                         Bw + (long)(bn + r) * Ka + it * 16 + q * 4);
                }
                CP_COMMIT();
            };

            load_stage(0, 0);
            for (int it = 0; it < nit; it++) {
                CP_WAIT0();
                __syncthreads();
                if (it + 1 < nit) load_stage(it + 1, (it + 1) & 1);
                const int p = it & 1;
                const float* Ab = As + p * G_ASZ + (wm * 32) * PAD_K;
                const float* Bb = Bs + p * G_BSZ + (wn * 64) * PAD_K;
#pragma unroll
                for (int ks = 0; ks < 2; ks++) {
                    const int k0 = ks * 8;
                    uint32_t afr[2][4];
#pragma unroll
                    for (int mt = 0; mt < 2; mt++) {
                        const float* r0 = Ab + (mt * 16 + g) * PAD_K + k0 + t;
                        const float* r1 = r0 + 8 * PAD_K;
                        afr[mt][0] = __float_as_uint(r0[0]);
                        afr[mt][1] = __float_as_uint(r1[0]);
                        afr[mt][2] = __float_as_uint(r0[4]);
                        afr[mt][3] = __float_as_uint(r1[4]);
                    }
#pragma unroll
                    for (int nt = 0; nt < 8; nt++) {
                        const float* br = Bb + (nt * 8 + g) * PAD_K + k0 + t;
                        uint32_t b0 = __float_as_uint(br[0]);
                        uint32_t b1 = __float_as_uint(br[4]);
                        mma_tf32(c[0][nt], afr[0], b0, b1);
                        mma_tf32(c[1][nt], afr[1], b0, b1);
                    }
                }
                __syncthreads();
            }
#pragma unroll
            for (int mt = 0; mt < 2; mt++) {
                const int row = bm + wm * 32 + mt * 16 + g;
#pragma unroll
                for (int nt = 0; nt < 8; nt++) {
                    const int col = bn + wn * 64 + nt * 8 + 2 * t;
                    float2 bb = *(const float2*)(bias + col);
                    *(float2*)(Cgm + (long)row * ldc + col) =
                        make_float2(c[mt][nt][0] + bb.x, c[mt][nt][1] + bb.y);
                    *(float2*)(Cgm + (long)(row + 8) * ldc + col) =
                        make_float2(c[mt][nt][2] + bb.x, c[mt][nt][3] + bb.y);
                }
            }
            __threadfence();
            __syncthreads();
            if (tid == 0) atomicAdd(&cnt[b * 4 + tc], 1);
        }
        return;
    }

    // ======================= scan consumer role =======================
    uint32_t* Hsh2 = (uint32_t*)k_smem;                  // [2][MR][HP] fp16x2
    float* Xs = (float*)k_smem + 2 * MR * HP;            // [4][MR][XsP]

    const int lane = tid & 31, w = tid >> 5;
    const int gq = lane >> 2, c4 = lane & 3;
    int dir, chunk;
    if (NDIR == 2) { dir = blockIdx.x & 1; chunk = blockIdx.x >> 1; }
    else           { dir = 0;              chunk = blockIdx.x; }
    const int row0 = chunk * MR;
    const float* whh = (dir == 0) ? whh_f : whh_r;
    const int goff = (NDIR == 2) ? dir * 512 : 0;
    const float* xg = Cgm;
    const int gst = ldc;
    const long sgn = (dir == 0) ? (long)gst : -(long)gst;

    auto wait_chunk = [&](int tc) {
        if (tid < MR) {
            volatile int* p = cnt + (row0 + tid) * 4 + tc;
            while (*p < nNt) __nanosleep(200);
            __threadfence();
        }
        __syncthreads();
    };

    // pack w_hh B-fragments (fp16), once; nt indexes the GATE block
    uint32_t bfrag[4][8][2];
#pragma unroll
    for (int nt = 0; nt < 4; nt++) {
        const int n = nt * 128 + w * 8 + gq;
        const float* wp = whh + n * 128;
#pragma unroll
        for (int kt = 0; kt < 8; kt++) {
            float2 v0 = *(const float2*)(wp + kt * 16 + 2 * c4);
            float2 v1 = *(const float2*)(wp + kt * 16 + 2 * c4 + 8);
            bfrag[nt][kt][0] = f2h2(v0.x, v0.y);
            bfrag[nt][kt][1] = f2h2(v1.x, v1.y);
        }
    }
    for (int i = tid; i < MR * HP; i += 512) Hsh2[i] = 0;

    const int hr0 = (2 * tid) >> 7, hc0 = ((2 * tid) & 127) * 4;
    const int hr1 = (2 * tid + 1) >> 7, hc1 = ((2 * tid + 1) & 127) * 4;
    const int t0 = (dir == 0) ? 0 : (T_SEQ - 1);

    // hoisted, incrementing GMEM pointers (always point at next t to prefetch)
    const float* xp0 = xg + ((long)(row0 + hr0) * T_SEQ + t0) * gst + goff + hc0;
    const float* xp1 = xg + ((long)(row0 + hr1) * T_SEQ + t0) * gst + goff + hc1;
    const int j0 = w * 8 + 2 * c4;
    float* outp = WRITE_ALL
        ? out + ((long)(row0 + gq) * T_SEQ + t0) * 256 + dir * 128 + j0
        : out + (row0 + gq) * 256 + j0;
    const long osgn = (dir == 0) ? 256L : -256L;

    // wait for first chunk, then prefetch steps 0 and 1 (distance-2 pipeline)
    wait_chunk((dir == 0) ? 0 : 3);
    cp16(&Xs[0 * (MR * XsP) + hr0 * XsP + hc0], xp0);
    cp16(&Xs[0 * (MR * XsP) + hr1 * XsP + hc1], xp1);
    CP_COMMIT();
    xp0 += sgn; xp1 += sgn;
    cp16(&Xs[1 * (MR * XsP) + hr0 * XsP + hc0], xp0);
    cp16(&Xs[1 * (MR * XsP) + hr1 * XsP + hc1], xp1);
    CP_COMMIT();
    xp0 += sgn; xp1 += sgn;
    CP_WAIT1();           // buffer 0 ready
    __syncthreads();

    float cr0 = 0.f, cr1 = 0.f;

    auto step_body = [&](int s, int hr, int hw, int xr, int xw) {
        const uint32_t* Hrd = Hsh2 + hr * (MR * HP);
        uint32_t* Hwr = Hsh2 + hw * (MR * HP);
        const float* Xrd = Xs + xr * (MR * XsP);
        float* Xwr = Xs + xw * (MR * XsP);

        // prefetch step s+2 (distance-2; its chunk must be ready first)
        if (s + 2 < T_SEQ) {
            if (((s + 2) & 127) == 0)
                wait_chunk((dir == 0) ? ((s + 2) >> 7) : (3 - ((s + 2) >> 7)));
            cp16(&Xwr[hr0 * XsP + hc0], xp0);
            cp16(&Xwr[hr1 * XsP + hc1], xp1);
            xp0 += sgn; xp1 += sgn;
        }
        CP_COMMIT();

        // gate MMA: 4 gate blocks x 8 k-tiles
        float cf[4][2];
#pragma unroll
        for (int nt = 0; nt < 4; nt++) { cf[nt][0] = 0.f; cf[nt][1] = 0.f; }
        float dz0 = 0.f, dz1 = 0.f;
#pragma unroll
        for (int kt = 0; kt < 8; kt++) {
            uint32_t a0 = Hrd[gq * HP + kt * 8 + c4];
            uint32_t a2 = Hrd[gq * HP + kt * 8 + c4 + 4];
#pragma unroll
            for (int nt = 0; nt < 4; nt++)
                mma_f16(cf[nt][0], cf[nt][1], dz0, dz1,
                        a0, 0u, a2, 0u, bfrag[nt][kt][0], bfrag[nt][kt][1]);
        }

        // in-register cell update (2 cells), xg from staged smem; direct h store
        float2 xi = *(const float2*)&Xrd[gq * XsP + j0];
        float2 xf = *(const float2*)&Xrd[gq * XsP + 128 + j0];
        float2 xgv = *(const float2*)&Xrd[gq * XsP + 256 + j0];
        float2 xo = *(const float2*)&Xrd[gq * XsP + 384 + j0];
        float h0, h1;
        lstm_cell(cf[0][0] + xi.x, cf[1][0] + xf.x, cf[2][0] + xgv.x, cf[3][0] + xo.x, cr0, h0);
        lstm_cell(cf[0][1] + xi.y, cf[1][1] + xf.y, cf[2][1] + xgv.y, cf[3][1] + xo.y, cr1, h1);
        Hwr[gq * HP + w * 4 + c4] = f2h2(h0, h1);
        if (WRITE_ALL) {
            *(float2*)outp = make_float2(rtf32(h0), rtf32(h1));
            outp += osgn;
        } else if (s == T_SEQ - 1) {
            *(float2*)outp = make_float2(h0, h1);
        }
        CP_WAIT1();       // step s+1's xg (issued at s-1) now resident
        __syncthreads();
    };

    for (int s = 0; s < T_SEQ; s += 4) {
        step_body(s + 0, 0, 1, 0, 2);
        step_body(s + 1, 1, 0, 1, 3);
        step_body(s + 2, 0, 1, 2, 0);
        step_body(s + 3, 1, 0, 3, 1);
    }
}

// ---------------- layer1 reverse: single step with h0=0 -> pure elementwise ----------------
__global__ void l1rev_kernel() {
    int idx = blockIdx.x * blockDim.x + threadIdx.x;
    if (idx >= 128 * 128) return;
    int b = idx >> 7, j = idx & 127;
    const float* xg = g_xg1r + b * 512;
    float c = sigf(xg[j]) * tanhap(xg[256 + j]);
    g_h1last[b * 256 + 128 + j] = sigf(xg[384 + j]) * tanhap(c);
}

// ---------------- final FC ----------------
__global__ void fc_kernel(const float* __restrict__ fcw, const float* __restrict__ fcb,
                          float* __restrict__ out) {
    int b = blockIdx.x;
    int lane = threadIdx.x;
    float v[8];
#pragma unroll
    for (int u = 0; u < 8; u++) v[u] = g_h1last[b * 256 + lane + u * 32];
    for (int c = 0; c < 10; c++) {
        float s = 0.f;
#pragma unroll
        for (int u = 0; u < 8; u++) s = fmaf(v[u], fcw[c * 256 + lane + u * 32], s);
#pragma unroll
        for (int o = 16; o; o >>= 1) s += __shfl_xor_sync(0xffffffffu, s, o);
        if (lane == 0) out[b * 10 + c] = s + fcb[c];
    }
}

// ---------------- launch ----------------
extern "C" void kernel_launch(void* const* d_in, const int* in_sizes, int n_in,
                              void* d_out, int out_size) {
    const int*   x        = (const int*)d_in[0];
    const float* emb      = (const float*)d_in[1];
    const float* wih_l0f  = (const float*)d_in[2];
    const float* whh_l0f  = (const float*)d_in[3];
    const float* bih_l0f  = (const float*)d_in[4];
    const float* bhh_l0f  = (const float*)d_in[5];
    const float* wih_l0r  = (const float*)d_in[6];
    const float* whh_l0r  = (const float*)d_in[7];
    const float* bih_l0r  = (const float*)d_in[8];
    const float* bhh_l0r  = (const float*)d_in[9];
    const float* wih_l1f  = (const float*)d_in[10];
    const float* whh_l1f  = (const float*)d_in[11];
    const float* bih_l1f  = (const float*)d_in[12];
    const float* bhh_l1f  = (const float*)d_in[13];
    const float* wih_l1r  = (const float*)d_in[14];
    const float* bih_l1r  = (const float*)d_in[16];
    const float* bhh_l1r  = (const float*)d_in[17];
    const float* fc_w     = (const float*)d_in[18];
    const float* fc_b     = (const float*)d_in[19];
    float* out = (float*)d_out;

    float *pX0, *pWpad, *pW1, *pB0, *pB1f, *pB1r, *pXg0, *pHs0, *pXg1f, *pXg1r, *pH1;
    int *pCnt0, *pCnt1;
    cudaGetSymbolAddress((void**)&pX0,   g_X0);
    cudaGetSymbolAddress((void**)&pWpad, g_Wpad);
    cudaGetSymbolAddress((void**)&pW1,   g_W1);
    cudaGetSymbolAddress((void**)&pB0,   g_bias0);
    cudaGetSymbolAddress((void**)&pB1f,  g_bias1f);
    cudaGetSymbolAddress((void**)&pB1r,  g_bias1r);
    cudaGetSymbolAddress((void**)&pXg0,  g_xg0);
    cudaGetSymbolAddress((void**)&pHs0,  g_hs0);
    cudaGetSymbolAddress((void**)&pXg1f, g_xg1f);
    cudaGetSymbolAddress((void**)&pXg1r, g_xg1r);
    cudaGetSymbolAddress((void**)&pH1,   g_h1last);
    cudaGetSymbolAddress((void**)&pCnt0, g_cnt0);
    cudaGetSymbolAddress((void**)&pCnt1, g_cnt1);

    // scan role: 2*MR*HP + 4*MR*XsP floats = 4352 + 66048 B; GEMM role: 61440 B
    const int SMEM_FUSED = 71680;
    cudaFuncSetAttribute(fused_kernel<2, true>,
                         cudaFuncAttributeMaxDynamicSharedMemorySize, SMEM_FUSED);
    cudaFuncSetAttribute(fused_kernel<1, false>,
                         cudaFuncAttributeMaxDynamicSharedMemorySize, SMEM_FUSED);

    prep_kernel<<<128, 256>>>(wih_l0f, wih_l0r, wih_l1f,
                              bih_l0f, bhh_l0f, bih_l0r, bhh_l0r,
                              bih_l1f, bhh_l1f, bih_l1r, bhh_l1r);
    embed_kernel<<<2048, 256>>>(x, emb);

    // fused layer0: GEMM [65536,304]x[1024,304]^T producer + bi-dir scan consumer
    fused_kernel<2, true><<<148, 512, SMEM_FUSED>>>(
        32, pX0, KPAD, pWpad, pXg0, 1024, 4, pB0, pCnt0,
        whh_l0f, whh_l0r, pHs0);

    // layer 1 reverse: only t=T-1 row needed -> tiny GEMM + 1-step elementwise
    {
        dim3 grid(512 / 64, 1);
        gemm_bias_kernel<<<grid, 256>>>(pHs0 + 511 * 256, T_SEQ * 256, wih_l1r, 256,
                                        pXg1r, 512, 256, pB1r);
    }
    l1rev_kernel<<<64, 256>>>();

    // fused layer1 fwd: GEMM [65536,256]x[512,256]^T producer + fwd scan consumer
    fused_kernel<1, false><<<148, 512, SMEM_FUSED>>>(
        16, pHs0, 256, pW1, pXg1f, 512, 2, pB1f, pCnt1,
        whh_l1f, whh_l1f, pH1);

    fc_kernel<<<128, 32>>>(fc_w, fc_b, out);
    (void)in_sizes; (void)n_in; (void)out_size;
}